// round 12
// baseline (speedup 1.0000x reference)
#include <cuda_runtime.h>
#include <math.h>
#include <stdint.h>

#define BATCH 4096
#define DX 128
#define TT 81
#define DH 1024
#define KIN 257
#define KINP 288
#define DD 128
#define NSTEP 64
#define NDLY 16
#define DTC 0.02f
#define EPSB 1e-5f

#define KT_IN 36
#define KT_H  128

/* B planes: interleaved hi/lo per lane: [ntile][ktile][lane][b0h,b1h,b0l,b1l] */
#define BIN_OFF  0
#define BIN_SZ   (128 * KT_IN * 128)
#define BH_OFF   (BIN_OFF + BIN_SZ)
#define BH_SZ    (128 * KT_H * 128)
#define BOUT_OFF (BH_OFF + 3 * BH_SZ)
#define BOUT_SZ  (16 * KT_H * 128)
#define BSP_TOTAL (BOUT_OFF + BOUT_SZ)

#define STAGE 65536            /* Araw 32K | B 32K (K-chunk = 32) */
#define GEMM_SMEM (2 * STAGE)

#define A_IN_STRIDE  ((size_t)BATCH * KINP)
#define A_H_STRIDE   ((size_t)BATCH * DH)
#define ZT_STRIDE    ((size_t)BATCH * DD)

// ---------------- device scratch ----------------
__device__ float g_Bsp[BSP_TOTAL];
__device__ float g_bufA[(size_t)NSTEP * BATCH * DH];
__device__ float g_bufB[(size_t)NSTEP * BATCH * DH];
__device__ float g_zt[(size_t)NSTEP * BATCH * DD];
__device__ float g_xT[(size_t)BATCH * TT * DX];
__device__ float g_dWT[(size_t)BATCH * NSTEP * DD];
__device__ float g_xrow[BATCH * TT];
__device__ float g_cs[4 * NSTEP * DH];
__device__ float g_cq[4 * NSTEP * DH];
__device__ float g_xsum[DX * TT];
__device__ float g_xsq[DX * TT];
__device__ float g_C1[NSTEP * BATCH];
__device__ float g_S2[NSTEP * BATCH];

// ---------------- helpers ----------------
__device__ __forceinline__ uint32_t smem_u32(const void* p) {
    uint32_t a;
    asm("{ .reg .u64 t; cvta.to.shared.u64 t, %1; cvt.u32.u64 %0, t; }" : "=r"(a) : "l"(p));
    return a;
}
__device__ __forceinline__ uint32_t tf32_rna(float x) {
    uint32_t u; asm("cvt.rna.tf32.f32 %0, %1;" : "=r"(u) : "f"(x)); return u;
}
__device__ __forceinline__ void split_tf32(float x, uint32_t& h, uint32_t& l) {
    h = tf32_rna(x);
    l = tf32_rna(x - __uint_as_float(h));
}
__device__ __forceinline__ void lds64(uint32_t* r, uint32_t a) {
    asm volatile("ld.shared.v2.b32 {%0,%1}, [%2];" : "=r"(r[0]), "=r"(r[1]) : "r"(a));
}
__device__ __forceinline__ void lds128f(float* r, uint32_t a) {
    asm volatile("ld.shared.v4.f32 {%0,%1,%2,%3}, [%4];"
                 : "=f"(r[0]), "=f"(r[1]), "=f"(r[2]), "=f"(r[3]) : "r"(a));
}
__device__ __forceinline__ void cpasync16(uint32_t s, const void* g) {
    asm volatile("cp.async.cg.shared.global [%0], [%1], 16;" :: "r"(s), "l"(g));
}
#define CP_COMMIT() asm volatile("cp.async.commit_group;" ::: "memory")
#define CP_WAIT1()  asm volatile("cp.async.wait_group 1;" ::: "memory")
#define CP_WAIT0()  asm volatile("cp.async.wait_group 0;" ::: "memory")

__device__ __forceinline__ void mma8(float* d, const uint32_t* a, uint32_t b0, uint32_t b1) {
    asm volatile(
        "mma.sync.aligned.m16n8k8.row.col.f32.tf32.tf32.f32 "
        "{%0,%1,%2,%3}, {%4,%5,%6,%7}, {%8,%9}, {%0,%1,%2,%3};"
        : "+f"(d[0]), "+f"(d[1]), "+f"(d[2]), "+f"(d[3])
        : "r"(a[0]), "r"(a[1]), "r"(a[2]), "r"(a[3]), "r"(b0), "r"(b1));
}

// ---------------- mega setup: xstats | zero | xT | dWT | xrow | split_w ----------------
#define R0 (DX * TT)
#define R1 64
#define R2 (BATCH * 12)
#define R3 (BATCH * 8)
#define R4 BATCH
#define R5 13952

__global__ void mega_setup_kernel(const float* __restrict__ x, const float* __restrict__ dW,
                                  const float* __restrict__ W_in, const float* __restrict__ Ws_h,
                                  const float* __restrict__ W_out) {
    int b = blockIdx.x;
    if (b < R0) {
        int d = b / TT, j = b % TT;
        float s = 0.f, q = 0.f;
        const float* base = x + (size_t)d * TT + j;
        for (int r = 0; r < 16; r++) {
            float v = base[(size_t)(threadIdx.x + r * 256) * DX * TT];
            s += v; q += v * v;
        }
#pragma unroll
        for (int off = 16; off; off >>= 1) {
            s += __shfl_down_sync(0xffffffffu, s, off);
            q += __shfl_down_sync(0xffffffffu, q, off);
        }
        __shared__ float rs[8], rq[8];
        int w = threadIdx.x >> 5;
        if ((threadIdx.x & 31) == 0) { rs[w] = s; rq[w] = q; }
        __syncthreads();
        if (threadIdx.x == 0) {
            float a = 0.f, c = 0.f;
#pragma unroll
            for (int u = 0; u < 8; u++) { a += rs[u]; c += rq[u]; }
            g_xsum[d * TT + j] = a;
            g_xsq[d * TT + j] = c;
        }
        return;
    }
    b -= R0;
    if (b < R1) {
        int base = b * (4 * NSTEP * DH / R1);
        for (int i = threadIdx.x; i < 4 * NSTEP * DH / R1; i += 256) {
            g_cs[base + i] = 0.f;
            g_cq[base + i] = 0.f;
        }
        return;
    }
    b -= R1;
    if (b < R2) {
        __shared__ float tile[32][33];
        int bb = b / 12, r = b % 12;
        int ttile = r / 4, ktile = r % 4;
        int lane = threadIdx.x & 31, row4 = threadIdx.x >> 5;
#pragma unroll
        for (int rr = row4; rr < 32; rr += 8) {
            int k = ktile * 32 + rr;
            int t = ttile * 32 + lane;
            tile[rr][lane] = (t < TT) ? x[(size_t)bb * DX * TT + (size_t)k * TT + t] : 0.f;
        }
        __syncthreads();
#pragma unroll
        for (int rr = row4; rr < 32; rr += 8) {
            int t = ttile * 32 + rr;
            int k = ktile * 32 + lane;
            if (t < TT) g_xT[(size_t)bb * TT * DX + (size_t)t * DX + k] = tile[lane][rr];
        }
        return;
    }
    b -= R2;
    if (b < R3) {
        __shared__ float tile[32][33];
        int bb = b / 8, r = b % 8;
        int itile = r / 4, dtile = r % 4;
        int lane = threadIdx.x & 31, row4 = threadIdx.x >> 5;
#pragma unroll
        for (int rr = row4; rr < 32; rr += 8) {
            int dcol = dtile * 32 + rr;
            int i = itile * 32 + lane;
            tile[rr][lane] = dW[(size_t)bb * DD * NSTEP + (size_t)dcol * NSTEP + i];
        }
        __syncthreads();
#pragma unroll
        for (int rr = row4; rr < 32; rr += 8) {
            int i = itile * 32 + rr;
            int dcol = dtile * 32 + lane;
            g_dWT[(size_t)bb * NSTEP * DD + (size_t)i * DD + dcol] = tile[lane][rr];
        }
        return;
    }
    b -= R3;
    if (b < R4) {
        int t = threadIdx.x;
        if (t < TT) {
            float s = 0.f;
            const float* base = x + (size_t)b * DX * TT + t;
            for (int d = 0; d < DX; d++) s += base[(size_t)d * TT];
            g_xrow[b * TT + t] = s;
        }
        return;
    }
    b -= R4;
    {
        size_t i = (size_t)b * 256 + threadIdx.x;
        const size_t N_IN = (size_t)KINP * DH;
        const size_t N_H  = (size_t)DH * DH;
        const size_t N_O  = (size_t)DH * DD;
        if (i >= N_IN + 3 * N_H + N_O) return;
        int k, n, Kt; size_t base; float v;
        if (i < N_IN) {
            k = (int)(i / DH); n = (int)(i % DH);
            v = (k < KIN) ? W_in[(size_t)k * DH + n] : 0.f;
            Kt = KT_IN; base = BIN_OFF;
        } else if (i < N_IN + 3 * N_H) {
            size_t j = i - N_IN;
            int l = (int)(j / N_H); size_t r = j % N_H;
            k = (int)(r / DH); n = (int)(r % DH);
            v = Ws_h[(size_t)l * N_H + (size_t)k * DH + n];
            Kt = KT_H; base = BH_OFF + (size_t)l * BH_SZ;
        } else {
            size_t j = i - N_IN - 3 * N_H;
            k = (int)(j / DD); n = (int)(j % DD);
            v = W_out[(size_t)k * DD + n];
            Kt = KT_H; base = BOUT_OFF;
        }
        uint32_t h, l2;
        split_tf32(v, h, l2);
        int nt = n >> 3, kt = k >> 3;
        int lane = (n & 7) * 4 + (k & 3);
        int w = (k & 7) >> 2;
        size_t off = base + ((size_t)(nt * Kt + kt) * 32 + lane) * 4;
        g_Bsp[off + w]     = __uint_as_float(h);
        g_Bsp[off + w + 2] = __uint_as_float(l2);
    }
}

// ---------------- gather all steps (inline input-BN fold) -> raw t0 tiles ----------------
__global__ void gather_all_kernel(const float* __restrict__ gg, const float* __restrict__ bb) {
    int i = blockIdx.y;
    int it = i + NDLY;
    int idx = blockIdx.x * 256 + threadIdx.x;
    int lane = idx & 31;
    int t2 = idx >> 5;
    int kt = t2 % KT_IN, mt = t2 / KT_IN;
    int m0 = mt * 16 + (lane >> 2);
    int k0 = kt * 8 + (lane & 3);

    float av[2], cv[2];
#pragma unroll
    for (int h = 0; h < 2; h++) {
        int k = k0 + h * 4;
        float a = 0.f, c = 0.f;
        if (k < 2 * DX) {
            int d  = (k < DX) ? k  : k - DX;
            int tt = (k < DX) ? it : i;
            float s = __ldg(g_xsum + d * TT + tt), qq = __ldg(g_xsq + d * TT + tt);
            float m = s * (1.f / BATCH);
            float v = qq * (1.f / BATCH) - m * m;
            if (v < 0.f) v = 0.f;
            a = __ldg(gg + k) * rsqrtf(v + EPSB);
            c = __ldg(bb + k) - m * a;
        } else if (k == 2 * DX) {
            c = __ldg(bb + k);
        }
        av[h] = a; cv[h] = c;
    }

    const float* xr0 = g_xT + (size_t)m0 * TT * DX;
    const float* xr8 = g_xT + (size_t)(m0 + 8) * TT * DX;
    int k4 = k0 + 4;
    float r0 = 0.f, r1 = 0.f, r2 = 0.f, r3 = 0.f;
    if (k0 < DX)          { r0 = xr0[(size_t)it * DX + k0];       r1 = xr8[(size_t)it * DX + k0]; }
    else if (k0 < 2 * DX) { r0 = xr0[(size_t)i * DX + (k0 - DX)]; r1 = xr8[(size_t)i * DX + (k0 - DX)]; }
    if (k4 < DX)          { r2 = xr0[(size_t)it * DX + k4];       r3 = xr8[(size_t)it * DX + k4]; }
    else if (k4 < 2 * DX) { r2 = xr0[(size_t)i * DX + (k4 - DX)]; r3 = xr8[(size_t)i * DX + (k4 - DX)]; }

    float4 f;
    f.x = fmaf(r0, av[0], cv[0]);
    f.y = fmaf(r1, av[0], cv[0]);
    f.z = fmaf(r2, av[1], cv[1]);
    f.w = fmaf(r3, av[1], cv[1]);
    float* t0 = g_bufB + (size_t)i * A_IN_STRIDE;
    *(float4*)(t0 + ((size_t)(mt * KT_IN + kt) * 32 + lane) * 4) = f;
}

// ---------------- 3xTF32 GEMM: 4m x 4n warps (64x32 warp tile), K-chunk 32 ----------------
__global__ __launch_bounds__(512, 1)
void gemm_mma_kernel(const float* __restrict__ ApBase, int Kt, int chunks, size_t aStride,
                     const float* __restrict__ Bp,
                     const float* __restrict__ csPB, const float* __restrict__ cqPB,
                     const float* __restrict__ gg, const float* __restrict__ bb,
                     const float* __restrict__ bias,
                     float* __restrict__ outBase, size_t oStride, int ldo, int tile_out, int do_tanh,
                     float* __restrict__ csumB, float* __restrict__ csqB) {
    extern __shared__ float smf[];
    __shared__ float sa[DH], sc[DH];
    __shared__ float scol[128], ssq[128];
    const uint32_t sbase = smem_u32(smf);
    const int tid = threadIdx.x;
    const int step = blockIdx.z;
    const int mt0 = blockIdx.y * 16;
    const int nt0 = blockIdx.x * 16;
    const int w = tid >> 5, lane = tid & 31;
    const int wm = w & 3, wn = w >> 2;
    const bool fold = (csPB != nullptr);

    const float* Ap = ApBase + (size_t)step * aStride;
    float* out = outBase + (size_t)step * oStride;

    if (fold) {
        const float* csP = csPB + (size_t)step * DH;
        const float* cqP = cqPB + (size_t)step * DH;
        for (int k = tid; k < Kt * 8; k += 512) {
            float m = __ldg(csP + k) * (1.f / BATCH);
            float v = __ldg(cqP + k) * (1.f / BATCH) - m * m;
            if (v < 0.f) v = 0.f;
            float a = __ldg(gg + k) * rsqrtf(v + EPSB);
            sa[k] = a;
            sc[k] = __ldg(bb + k) - m * a;
        }
    } else {
        for (int k = tid; k < Kt * 8; k += 512) { sa[k] = 1.f; sc[k] = 0.f; }
    }
    __syncthreads();

    // stage layout: A [mt(16)][kt(4)][lane][4] = 32KB, then B [nt(16)][kt(4)][lane][4] = 32KB
#define LOAD_A(kc_, st_)                                                         \
    {                                                                            \
        uint32_t base_ = sbase + (st_) * STAGE;                                  \
        _Pragma("unroll")                                                        \
        for (int i_ = 0; i_ < 4; i_++) {                                         \
            int idx_ = i_ * 512 + tid;                                           \
            int mt_ = idx_ >> 7, kt_ = (idx_ >> 5) & 3, ln_ = idx_ & 31;         \
            const float* src_ = Ap + (((size_t)(mt0 + mt_) * Kt + (kc_) * 4 + kt_) * 32 + ln_) * 4; \
            cpasync16(base_ + (uint32_t)((((mt_ * 4 + kt_) * 32 + ln_) * 4) * 4), src_); \
        }                                                                        \
    }
#define LOAD_B(kc_, st_)                                                         \
    {                                                                            \
        uint32_t bb_ = sbase + (st_) * STAGE + 32768;                            \
        _Pragma("unroll")                                                        \
        for (int i_ = 0; i_ < 4; i_++) {                                         \
            int idx_ = i_ * 512 + tid;                                           \
            int nt_ = idx_ >> 7, kt_ = (idx_ >> 5) & 3, ln_ = idx_ & 31;         \
            const float* src_ = Bp + ((size_t)(nt0 + nt_) * Kt + (kc_) * 4 + kt_) * 128 + ln_ * 4; \
            cpasync16(bb_ + (uint32_t)((((nt_ * 4 + kt_) * 32 + ln_) * 4) * 4), src_); \
        }                                                                        \
    }

    float acc[4][4][4];
#pragma unroll
    for (int mi = 0; mi < 4; mi++)
#pragma unroll
        for (int ni = 0; ni < 4; ni++)
#pragma unroll
            for (int r = 0; r < 4; r++) acc[mi][ni][r] = 0.f;

    LOAD_A(0, 0);
    LOAD_B(0, 0);
    CP_COMMIT();

    for (int kc = 0; kc < chunks; kc++) {
        const int st = kc & 1;
        if (kc + 1 < chunks) {
            LOAD_A(kc + 1, st ^ 1);
            LOAD_B(kc + 1, st ^ 1);
            CP_COMMIT();
            CP_WAIT1();
        } else {
            CP_WAIT0();
        }
        __syncthreads();

        const uint32_t abase = sbase + st * STAGE;
        const uint32_t bbase = abase + 32768;
#pragma unroll
        for (int kk = 0; kk < 4; kk++) {
            int kg = (kc * 4 + kk) * 8 + (lane & 3);
            float fa0 = sa[kg], fc0 = sc[kg];
            float fa4 = sa[kg + 4], fc4 = sc[kg + 4];

            uint32_t ah[4][4], al[4][4];
#pragma unroll
            for (int mi = 0; mi < 4; mi++) {
                int mt = wm * 4 + mi;
                float ar[4];
                lds128f(ar, abase + (uint32_t)((((mt * 4 + kk) * 32 + lane) * 4) * 4));
                float f0 = fmaf(ar[0], fa0, fc0);
                float f1 = fmaf(ar[1], fa0, fc0);
                float f2 = fmaf(ar[2], fa4, fc4);
                float f3 = fmaf(ar[3], fa4, fc4);
                split_tf32(f0, ah[mi][0], al[mi][0]);
                split_tf32(f1, ah[mi][1], al[mi][1]);
                split_tf32(f2, ah[mi][2], al[mi][2]);
                split_tf32(f3, ah[mi][3], al[mi][3]);
            }
            uint32_t bf[4][2];
#pragma unroll
            for (int ni = 0; ni < 4; ni++) {
                int nt = wn * 4 + ni;
                lds64(bf[ni], bbase + (uint32_t)((((nt * 4 + kk) * 32 + lane) * 4) * 4));
            }
#pragma unroll
            for (int ni = 0; ni < 4; ni++)
#pragma unroll
                for (int mi = 0; mi < 4; mi++)
                    mma8(acc[mi][ni], ah[mi], bf[ni][0], bf[ni][1]);   // hi*hi
#pragma unroll
            for (int ni = 0; ni < 4; ni++)
#pragma unroll
                for (int mi = 0; mi < 4; mi++)
                    mma8(acc[mi][ni], al[mi], bf[ni][0], bf[ni][1]);   // lo*hi
#pragma unroll
            for (int ni = 0; ni < 4; ni++) {
                int nt = wn * 4 + ni;
                lds64(bf[ni], bbase + (uint32_t)((((nt * 4 + kk) * 32 + lane) * 4) * 4) + 8);
            }
#pragma unroll
            for (int ni = 0; ni < 4; ni++)
#pragma unroll
                for (int mi = 0; mi < 4; mi++)
                    mma8(acc[mi][ni], ah[mi], bf[ni][0], bf[ni][1]);   // hi*lo
        }
        __syncthreads();
    }

    const int r = lane >> 2, q = lane & 3;
    float colacc[4][4];
#pragma unroll
    for (int ni = 0; ni < 4; ni++)
#pragma unroll
        for (int u = 0; u < 4; u++) colacc[ni][u] = 0.f;

#pragma unroll
    for (int mi = 0; mi < 4; mi++) {
        int m = blockIdx.y * 256 + (wm * 4 + mi) * 16 + r;
#pragma unroll
        for (int ni = 0; ni < 4; ni++) {
            int n = nt0 * 8 + (wn * 4 + ni) * 8 + 2 * q;
            float b0 = __ldg(bias + n), b1 = __ldg(bias + n + 1);
            float v0 = acc[mi][ni][0] + b0;
            float v1 = acc[mi][ni][1] + b1;
            float v2 = acc[mi][ni][2] + b0;
            float v3 = acc[mi][ni][3] + b1;
            if (do_tanh) { v0 = tanhf(v0); v1 = tanhf(v1); v2 = tanhf(v2); v3 = tanhf(v3); }
            colacc[ni][0] += v0 + v2;
            colacc[ni][1] += v1 + v3;
            colacc[ni][2] += v0 * v0 + v2 * v2;
            colacc[ni][3] += v1 * v1 + v3 * v3;
            if (tile_out) {
                int base = ((((m >> 4) * KT_H + (n >> 3)) * 32 + (m & 7) * 4 + (n & 3)) << 2)
                         + 2 * ((n >> 2) & 1);
                *(float2*)(out + base)     = make_float2(v0, v2);
                *(float2*)(out + base + 4) = make_float2(v1, v3);
            } else {
                *(float2*)(out + (size_t)m * ldo + n) = make_float2(v0, v1);
                *(float2*)(out + (size_t)(m + 8) * ldo + n) = make_float2(v2, v3);
            }
        }
    }

    if (csumB != nullptr) {
        float* csum = csumB + (size_t)step * DH;
        float* csq  = csqB + (size_t)step * DH;
        if (tid < 128) { scol[tid] = 0.f; ssq[tid] = 0.f; }
        __syncthreads();
#pragma unroll
        for (int ni = 0; ni < 4; ni++) {
            float a0 = colacc[ni][0], a1 = colacc[ni][1];
            float q0 = colacc[ni][2], q1 = colacc[ni][3];
#pragma unroll
            for (int off = 4; off < 32; off <<= 1) {
                a0 += __shfl_xor_sync(0xffffffffu, a0, off);
                a1 += __shfl_xor_sync(0xffffffffu, a1, off);
                q0 += __shfl_xor_sync(0xffffffffu, q0, off);
                q1 += __shfl_xor_sync(0xffffffffu, q1, off);
            }
            if (r == 0) {
                int cn = wn * 32 + ni * 8 + 2 * q;
                atomicAdd(&scol[cn], a0);
                atomicAdd(&scol[cn + 1], a1);
                atomicAdd(&ssq[cn], q0);
                atomicAdd(&ssq[cn + 1], q1);
            }
        }
        __syncthreads();
        if (tid < 128) {
            int col = blockIdx.x * 128 + tid;
            atomicAdd(csum + col, scol[tid]);
            atomicAdd(csq + col, ssq[tid]);
        }
    }
#undef LOAD_A
#undef LOAD_B
}

// ---------------- reductions / scatter / y recursion ----------------
__global__ void s_kernel() {
    int b = blockIdx.x, i = blockIdx.y, d = threadIdx.x;
    float zt = g_zt[((size_t)i * BATCH + b) * DD + d];
    float zd = (i > NDLY) ? g_zt[((size_t)(i - NDLY - 1) * BATCH + b) * DD + d] : 0.f;
    float dw = g_dWT[((size_t)b * NSTEP + i) * DD + d];
    float p1 = zt * zd;
    float p2 = zt * dw;
#pragma unroll
    for (int off = 16; off; off >>= 1) {
        p1 += __shfl_down_sync(0xffffffffu, p1, off);
        p2 += __shfl_down_sync(0xffffffffu, p2, off);
    }
    __shared__ float red[2][4];
    int w = d >> 5, lane = d & 31;
    if (lane == 0) { red[0][w] = p1; red[1][w] = p2; }
    __syncthreads();
    if (d == 0) {
        float s1 = red[0][0] + red[0][1] + red[0][2] + red[0][3];
        float s2 = red[1][0] + red[1][1] + red[1][2] + red[1][3];
        g_C1[i * BATCH + b] = s1 + 0.01f * g_xrow[b * TT + i + NDLY];
        g_S2[i * BATCH + b] = s2;
    }
}

__global__ void zscatter_kernel(float* __restrict__ z) {
    __shared__ float sm[NSTEP][DD + 1];
    int b = blockIdx.x;
    for (int q = threadIdx.x; q < NSTEP * DD; q += 256) {
        int i = q >> 7, d = q & 127;
        sm[i][d] = g_zt[((size_t)i * BATCH + b) * DD + d];
    }
    __syncthreads();
    for (int q = threadIdx.x; q < DD * TT; q += 256) {
        int d = q / TT, t = q - d * TT;
        float v = (t <= NDLY) ? 0.f : sm[t - NDLY - 1][d];
        z[(size_t)b * DD * TT + q] = v;
    }
}

__global__ void yrec_kernel(const float* __restrict__ y0, float* __restrict__ yt,
                            float* __restrict__ y) {
    int b = blockIdx.x * 256 + threadIdx.x;
    if (b >= BATCH) return;
    float y0v = __ldg(y0);
    float ycur = y0v;
    float yh[NSTEP];
    for (int t = 0; t <= NDLY; t++) y[b * TT + t] = y0v;
#pragma unroll 1
    for (int i = 0; i < NSTEP; i++) {
        float yd = (i <= NDLY) ? y0v : yh[i - NDLY - 1];
        float drv = -ycur + 0.1f * yd + g_C1[i * BATCH + b];
        ycur = ycur - drv * DTC + g_S2[i * BATCH + b];
        yh[i] = ycur;
        y[b * TT + NDLY + 1 + i] = ycur;
    }
    yt[b] = ycur;
}

// ---------------- host launch ----------------
static float* sym_addr(const void* sym) {
    void* p = nullptr;
    cudaGetSymbolAddress(&p, sym);
    return (float*)p;
}

extern "C" void kernel_launch(void* const* d_in, const int* in_sizes, int n_in,
                              void* d_out, int out_size) {
    const float* x        = (const float*)d_in[0];
    const float* dW       = (const float*)d_in[1];
    const float* y0       = (const float*)d_in[2];
    const float* bn_in_g  = (const float*)d_in[3];
    const float* bn_in_b  = (const float*)d_in[4];
    const float* W_in     = (const float*)d_in[5];
    const float* b_in     = (const float*)d_in[6];
    const float* Ws_h     = (const float*)d_in[7];
    const float* bs_h     = (const float*)d_in[8];
    const float* bns_g    = (const float*)d_in[9];
    const float* bns_b    = (const float*)d_in[10];
    const float* bn_out_g = (const float*)d_in[11];
    const float* bn_out_b = (const float*)d_in[12];
    const float* W_out    = (const float*)d_in[13];
    const float* b_out    = (const float*)d_in[14];

    float* yt = (float*)d_out;
    float* y  = yt + BATCH;
    float* z  = y + (size_t)BATCH * TT;

    float* bufA = sym_addr(g_bufA);
    float* bufB = sym_addr(g_bufB);
    float* Bsp  = sym_addr(g_Bsp);
    float* zt   = sym_addr(g_zt);
    float* cs   = sym_addr(g_cs);
    float* cq   = sym_addr(g_cq);

    cudaFuncSetAttribute(gemm_mma_kernel, cudaFuncAttributeMaxDynamicSharedMemorySize, GEMM_SMEM);

    mega_setup_kernel<<<R0 + R1 + R2 + R3 + R4 + R5, 256>>>(x, dW, W_in, Ws_h, W_out);
    gather_all_kernel<<<dim3(1152, NSTEP), 256>>>(bn_in_g, bn_in_b);

    dim3 gridH(8, 16, NSTEP);
    dim3 gridO(1, 16, NSTEP);

    // input layer (no fold): bufB -> bufA, stats cs[0]   (chunks = 36/4 = 9)
    gemm_mma_kernel<<<gridH, 512, GEMM_SMEM>>>(bufB, KT_IN, KT_IN / 4, A_IN_STRIDE,
                                               Bsp + BIN_OFF,
                                               nullptr, nullptr, nullptr, nullptr,
                                               b_in, bufA, A_H_STRIDE, 0, 1, 1,
                                               cs + 0 * NSTEP * DH, cq + 0 * NSTEP * DH);
    // hidden 1: bufA -> bufB   (chunks = 128/4 = 32)
    gemm_mma_kernel<<<gridH, 512, GEMM_SMEM>>>(bufA, KT_H, KT_H / 4, A_H_STRIDE,
                                               Bsp + BH_OFF,
                                               cs + 0 * NSTEP * DH, cq + 0 * NSTEP * DH,
                                               bns_g + 0 * DH, bns_b + 0 * DH,
                                               bs_h + 0 * DH, bufB, A_H_STRIDE, 0, 1, 1,
                                               cs + 1 * NSTEP * DH, cq + 1 * NSTEP * DH);
    // hidden 2: bufB -> bufA
    gemm_mma_kernel<<<gridH, 512, GEMM_SMEM>>>(bufB, KT_H, KT_H / 4, A_H_STRIDE,
                                               Bsp + BH_OFF + BH_SZ,
                                               cs + 1 * NSTEP * DH, cq + 1 * NSTEP * DH,
                                               bns_g + 1 * DH, bns_b + 1 * DH,
                                               bs_h + 1 * DH, bufA, A_H_STRIDE, 0, 1, 1,
                                               cs + 2 * NSTEP * DH, cq + 2 * NSTEP * DH);
    // hidden 3: bufA -> bufB
    gemm_mma_kernel<<<gridH, 512, GEMM_SMEM>>>(bufA, KT_H, KT_H / 4, A_H_STRIDE,
                                               Bsp + BH_OFF + 2 * BH_SZ,
                                               cs + 2 * NSTEP * DH, cq + 2 * NSTEP * DH,
                                               bns_g + 2 * DH, bns_b + 2 * DH,
                                               bs_h + 2 * DH, bufB, A_H_STRIDE, 0, 1, 1,
                                               cs + 3 * NSTEP * DH, cq + 3 * NSTEP * DH);
    // output layer: bufB -> zt
    gemm_mma_kernel<<<gridO, 512, GEMM_SMEM>>>(bufB, KT_H, KT_H / 4, A_H_STRIDE,
                                               Bsp + BOUT_OFF,
                                               cs + 3 * NSTEP * DH, cq + 3 * NSTEP * DH,
                                               bn_out_g, bn_out_b,
                                               b_out, zt, ZT_STRIDE, DD, 0, 0,
                                               nullptr, nullptr);

    s_kernel<<<dim3(BATCH, NSTEP), DD>>>();
    zscatter_kernel<<<BATCH, 256>>>(z);
    yrec_kernel<<<(BATCH + 255) / 256, 256>>>(y0, yt, y);
}

// round 13
// speedup vs baseline: 1.0691x; 1.0691x over previous
#include <cuda_runtime.h>
#include <math.h>
#include <stdint.h>

#define BATCH 4096
#define DX 128
#define TT 81
#define DH 1024
#define KIN 257
#define KINP 288
#define DD 128
#define NSTEP 64
#define NDLY 16
#define DTC 0.02f
#define EPSB 1e-5f

#define KT_IN 36
#define KT_H  128

/* B planes: interleaved hi/lo per lane: [ntile][ktile][lane][b0h,b1h,b0l,b1l] */
#define BIN_OFF  0
#define BIN_SZ   (128 * KT_IN * 128)
#define BH_OFF   (BIN_OFF + BIN_SZ)
#define BH_SZ    (128 * KT_H * 128)
#define BOUT_OFF (BH_OFF + 3 * BH_SZ)
#define BOUT_SZ  (16 * KT_H * 128)
#define BSP_TOTAL (BOUT_OFF + BOUT_SZ)

#define STAGE 65536            /* Araw 32K | B 32K (K-chunk = 32) */
#define GEMM_SMEM (2 * STAGE)

#define A_IN_STRIDE  ((size_t)BATCH * KINP)
#define A_H_STRIDE   ((size_t)BATCH * DH)
#define ZT_STRIDE    ((size_t)BATCH * DD)

// ---------------- device scratch ----------------
__device__ float g_Bsp[BSP_TOTAL];
__device__ float g_bufA[(size_t)NSTEP * BATCH * DH];
__device__ float g_bufB[(size_t)NSTEP * BATCH * DH];
__device__ float g_zt[(size_t)NSTEP * BATCH * DD];
__device__ float g_xT[(size_t)BATCH * TT * DX];
__device__ float g_dWT[(size_t)BATCH * NSTEP * DD];
__device__ float g_xrow[BATCH * TT];
__device__ float g_cs[4 * NSTEP * DH];
__device__ float g_cq[4 * NSTEP * DH];
__device__ float g_xsum[DX * TT];
__device__ float g_xsq[DX * TT];
__device__ float g_C1[NSTEP * BATCH];
__device__ float g_S2[NSTEP * BATCH];

// ---------------- helpers ----------------
__device__ __forceinline__ uint32_t smem_u32(const void* p) {
    uint32_t a;
    asm("{ .reg .u64 t; cvta.to.shared.u64 t, %1; cvt.u32.u64 %0, t; }" : "=r"(a) : "l"(p));
    return a;
}
__device__ __forceinline__ uint32_t tf32_rna(float x) {
    uint32_t u; asm("cvt.rna.tf32.f32 %0, %1;" : "=r"(u) : "f"(x)); return u;
}
__device__ __forceinline__ void split_tf32(float x, uint32_t& h, uint32_t& l) {
    h = tf32_rna(x);
    l = tf32_rna(x - __uint_as_float(h));
}
__device__ __forceinline__ void lds128(uint32_t* r, uint32_t a) {
    asm volatile("ld.shared.v4.b32 {%0,%1,%2,%3}, [%4];"
                 : "=r"(r[0]), "=r"(r[1]), "=r"(r[2]), "=r"(r[3]) : "r"(a));
}
__device__ __forceinline__ void lds128f(float* r, uint32_t a) {
    asm volatile("ld.shared.v4.f32 {%0,%1,%2,%3}, [%4];"
                 : "=f"(r[0]), "=f"(r[1]), "=f"(r[2]), "=f"(r[3]) : "r"(a));
}
__device__ __forceinline__ void cpasync16(uint32_t s, const void* g) {
    asm volatile("cp.async.cg.shared.global [%0], [%1], 16;" :: "r"(s), "l"(g));
}
#define CP_COMMIT() asm volatile("cp.async.commit_group;" ::: "memory")
#define CP_WAIT1()  asm volatile("cp.async.wait_group 1;" ::: "memory")
#define CP_WAIT0()  asm volatile("cp.async.wait_group 0;" ::: "memory")

__device__ __forceinline__ void mma8(float* d, const uint32_t* a, uint32_t b0, uint32_t b1) {
    asm volatile(
        "mma.sync.aligned.m16n8k8.row.col.f32.tf32.tf32.f32 "
        "{%0,%1,%2,%3}, {%4,%5,%6,%7}, {%8,%9}, {%0,%1,%2,%3};"
        : "+f"(d[0]), "+f"(d[1]), "+f"(d[2]), "+f"(d[3])
        : "r"(a[0]), "r"(a[1]), "r"(a[2]), "r"(a[3]), "r"(b0), "r"(b1));
}

// ---------------- mega setup: xstats | zero | xT | dWT | xrow | split_w ----------------
#define R0 (DX * TT)
#define R1 64
#define R2 (BATCH * 12)
#define R3 (BATCH * 8)
#define R4 BATCH
#define R5 13952

__global__ void mega_setup_kernel(const float* __restrict__ x, const float* __restrict__ dW,
                                  const float* __restrict__ W_in, const float* __restrict__ Ws_h,
                                  const float* __restrict__ W_out) {
    int b = blockIdx.x;
    if (b < R0) {
        int d = b / TT, j = b % TT;
        float s = 0.f, q = 0.f;
        const float* base = x + (size_t)d * TT + j;
        for (int r = 0; r < 16; r++) {
            float v = base[(size_t)(threadIdx.x + r * 256) * DX * TT];
            s += v; q += v * v;
        }
#pragma unroll
        for (int off = 16; off; off >>= 1) {
            s += __shfl_down_sync(0xffffffffu, s, off);
            q += __shfl_down_sync(0xffffffffu, q, off);
        }
        __shared__ float rs[8], rq[8];
        int w = threadIdx.x >> 5;
        if ((threadIdx.x & 31) == 0) { rs[w] = s; rq[w] = q; }
        __syncthreads();
        if (threadIdx.x == 0) {
            float a = 0.f, c = 0.f;
#pragma unroll
            for (int u = 0; u < 8; u++) { a += rs[u]; c += rq[u]; }
            g_xsum[d * TT + j] = a;
            g_xsq[d * TT + j] = c;
        }
        return;
    }
    b -= R0;
    if (b < R1) {
        int base = b * (4 * NSTEP * DH / R1);
        for (int i = threadIdx.x; i < 4 * NSTEP * DH / R1; i += 256) {
            g_cs[base + i] = 0.f;
            g_cq[base + i] = 0.f;
        }
        return;
    }
    b -= R1;
    if (b < R2) {
        __shared__ float tile[32][33];
        int bb = b / 12, r = b % 12;
        int ttile = r / 4, ktile = r % 4;
        int lane = threadIdx.x & 31, row4 = threadIdx.x >> 5;
#pragma unroll
        for (int rr = row4; rr < 32; rr += 8) {
            int k = ktile * 32 + rr;
            int t = ttile * 32 + lane;
            tile[rr][lane] = (t < TT) ? x[(size_t)bb * DX * TT + (size_t)k * TT + t] : 0.f;
        }
        __syncthreads();
#pragma unroll
        for (int rr = row4; rr < 32; rr += 8) {
            int t = ttile * 32 + rr;
            int k = ktile * 32 + lane;
            if (t < TT) g_xT[(size_t)bb * TT * DX + (size_t)t * DX + k] = tile[lane][rr];
        }
        return;
    }
    b -= R2;
    if (b < R3) {
        __shared__ float tile[32][33];
        int bb = b / 8, r = b % 8;
        int itile = r / 4, dtile = r % 4;
        int lane = threadIdx.x & 31, row4 = threadIdx.x >> 5;
#pragma unroll
        for (int rr = row4; rr < 32; rr += 8) {
            int dcol = dtile * 32 + rr;
            int i = itile * 32 + lane;
            tile[rr][lane] = dW[(size_t)bb * DD * NSTEP + (size_t)dcol * NSTEP + i];
        }
        __syncthreads();
#pragma unroll
        for (int rr = row4; rr < 32; rr += 8) {
            int i = itile * 32 + rr;
            int dcol = dtile * 32 + lane;
            g_dWT[(size_t)bb * NSTEP * DD + (size_t)i * DD + dcol] = tile[lane][rr];
        }
        return;
    }
    b -= R3;
    if (b < R4) {
        int t = threadIdx.x;
        if (t < TT) {
            float s = 0.f;
            const float* base = x + (size_t)b * DX * TT + t;
            for (int d = 0; d < DX; d++) s += base[(size_t)d * TT];
            g_xrow[b * TT + t] = s;
        }
        return;
    }
    b -= R4;
    {
        size_t i = (size_t)b * 256 + threadIdx.x;
        const size_t N_IN = (size_t)KINP * DH;
        const size_t N_H  = (size_t)DH * DH;
        const size_t N_O  = (size_t)DH * DD;
        if (i >= N_IN + 3 * N_H + N_O) return;
        int k, n, Kt; size_t base; float v;
        if (i < N_IN) {
            k = (int)(i / DH); n = (int)(i % DH);
            v = (k < KIN) ? W_in[(size_t)k * DH + n] : 0.f;
            Kt = KT_IN; base = BIN_OFF;
        } else if (i < N_IN + 3 * N_H) {
            size_t j = i - N_IN;
            int l = (int)(j / N_H); size_t r = j % N_H;
            k = (int)(r / DH); n = (int)(r % DH);
            v = Ws_h[(size_t)l * N_H + (size_t)k * DH + n];
            Kt = KT_H; base = BH_OFF + (size_t)l * BH_SZ;
        } else {
            size_t j = i - N_IN - 3 * N_H;
            k = (int)(j / DD); n = (int)(j % DD);
            v = W_out[(size_t)k * DD + n];
            Kt = KT_H; base = BOUT_OFF;
        }
        uint32_t h, l2;
        split_tf32(v, h, l2);
        int nt = n >> 3, kt = k >> 3;
        int lane = (n & 7) * 4 + (k & 3);
        int w = (k & 7) >> 2;
        size_t off = base + ((size_t)(nt * Kt + kt) * 32 + lane) * 4;
        g_Bsp[off + w]     = __uint_as_float(h);
        g_Bsp[off + w + 2] = __uint_as_float(l2);
    }
}

// ---------------- gather all steps (inline input-BN fold) -> raw t0 tiles ----------------
__global__ void gather_all_kernel(const float* __restrict__ gg, const float* __restrict__ bb) {
    int i = blockIdx.y;
    int it = i + NDLY;
    int idx = blockIdx.x * 256 + threadIdx.x;
    int lane = idx & 31;
    int t2 = idx >> 5;
    int kt = t2 % KT_IN, mt = t2 / KT_IN;
    int m0 = mt * 16 + (lane >> 2);
    int k0 = kt * 8 + (lane & 3);

    float av[2], cv[2];
#pragma unroll
    for (int h = 0; h < 2; h++) {
        int k = k0 + h * 4;
        float a = 0.f, c = 0.f;
        if (k < 2 * DX) {
            int d  = (k < DX) ? k  : k - DX;
            int tt = (k < DX) ? it : i;
            float s = __ldg(g_xsum + d * TT + tt), qq = __ldg(g_xsq + d * TT + tt);
            float m = s * (1.f / BATCH);
            float v = qq * (1.f / BATCH) - m * m;
            if (v < 0.f) v = 0.f;
            a = __ldg(gg + k) * rsqrtf(v + EPSB);
            c = __ldg(bb + k) - m * a;
        } else if (k == 2 * DX) {
            c = __ldg(bb + k);
        }
        av[h] = a; cv[h] = c;
    }

    const float* xr0 = g_xT + (size_t)m0 * TT * DX;
    const float* xr8 = g_xT + (size_t)(m0 + 8) * TT * DX;
    int k4 = k0 + 4;
    float r0 = 0.f, r1 = 0.f, r2 = 0.f, r3 = 0.f;
    if (k0 < DX)          { r0 = xr0[(size_t)it * DX + k0];       r1 = xr8[(size_t)it * DX + k0]; }
    else if (k0 < 2 * DX) { r0 = xr0[(size_t)i * DX + (k0 - DX)]; r1 = xr8[(size_t)i * DX + (k0 - DX)]; }
    if (k4 < DX)          { r2 = xr0[(size_t)it * DX + k4];       r3 = xr8[(size_t)it * DX + k4]; }
    else if (k4 < 2 * DX) { r2 = xr0[(size_t)i * DX + (k4 - DX)]; r3 = xr8[(size_t)i * DX + (k4 - DX)]; }

    float4 f;
    f.x = fmaf(r0, av[0], cv[0]);
    f.y = fmaf(r1, av[0], cv[0]);
    f.z = fmaf(r2, av[1], cv[1]);
    f.w = fmaf(r3, av[1], cv[1]);
    float* t0 = g_bufB + (size_t)i * A_IN_STRIDE;
    *(float4*)(t0 + ((size_t)(mt * KT_IN + kt) * 32 + lane) * 4) = f;
}

// ---------------- 3xTF32 GEMM: 8m x 2n warps (32x64 warp tile), K-chunk 32 ----------------
__global__ __launch_bounds__(512, 1)
void gemm_mma_kernel(const float* __restrict__ ApBase, int Kt, int chunks, size_t aStride,
                     const float* __restrict__ Bp,
                     const float* __restrict__ csPB, const float* __restrict__ cqPB,
                     const float* __restrict__ gg, const float* __restrict__ bb,
                     const float* __restrict__ bias,
                     float* __restrict__ outBase, size_t oStride, int ldo, int tile_out, int do_tanh,
                     float* __restrict__ csumB, float* __restrict__ csqB) {
    extern __shared__ float smf[];
    __shared__ float sa[DH], sc[DH];
    __shared__ float scol[128], ssq[128];
    const uint32_t sbase = smem_u32(smf);
    const int tid = threadIdx.x;
    const int step = blockIdx.z;
    const int mt0 = blockIdx.y * 16;
    const int nt0 = blockIdx.x * 16;
    const int w = tid >> 5, lane = tid & 31;
    const int wm = w & 7, wn2 = w >> 3;
    const bool fold = (csPB != nullptr);

    const float* Ap = ApBase + (size_t)step * aStride;
    float* out = outBase + (size_t)step * oStride;

    if (fold) {
        const float* csP = csPB + (size_t)step * DH;
        const float* cqP = cqPB + (size_t)step * DH;
        for (int k = tid; k < Kt * 8; k += 512) {
            float m = __ldg(csP + k) * (1.f / BATCH);
            float v = __ldg(cqP + k) * (1.f / BATCH) - m * m;
            if (v < 0.f) v = 0.f;
            float a = __ldg(gg + k) * rsqrtf(v + EPSB);
            sa[k] = a;
            sc[k] = __ldg(bb + k) - m * a;
        }
    } else {
        for (int k = tid; k < Kt * 8; k += 512) { sa[k] = 1.f; sc[k] = 0.f; }
    }
    __syncthreads();

    // stage: A [mt(16)][kt(4)][lane][4] = 32KB | B [nt(16)][kt(4)][lane][4w] = 32KB
#define LOAD_A(kc_, st_)                                                         \
    {                                                                            \
        uint32_t base_ = sbase + (st_) * STAGE;                                  \
        _Pragma("unroll")                                                        \
        for (int i_ = 0; i_ < 4; i_++) {                                         \
            int idx_ = i_ * 512 + tid;                                           \
            int mt_ = idx_ >> 7, kt_ = (idx_ >> 5) & 3, ln_ = idx_ & 31;         \
            const float* src_ = Ap + (((size_t)(mt0 + mt_) * Kt + (kc_) * 4 + kt_) * 32 + ln_) * 4; \
            cpasync16(base_ + (uint32_t)((((mt_ * 4 + kt_) * 32 + ln_) * 4) * 4), src_); \
        }                                                                        \
    }
#define LOAD_B(kc_, st_)                                                         \
    {                                                                            \
        uint32_t bb_ = sbase + (st_) * STAGE + 32768;                            \
        _Pragma("unroll")                                                        \
        for (int i_ = 0; i_ < 4; i_++) {                                         \
            int idx_ = i_ * 512 + tid;                                           \
            int nt_ = idx_ >> 7, kt_ = (idx_ >> 5) & 3, ln_ = idx_ & 31;         \
            const float* src_ = Bp + ((size_t)(nt0 + nt_) * Kt + (kc_) * 4 + kt_) * 128 + ln_ * 4; \
            cpasync16(bb_ + (uint32_t)((((nt_ * 4 + kt_) * 32 + ln_) * 4) * 4), src_); \
        }                                                                        \
    }

    float acc[2][8][4];
#pragma unroll
    for (int mi = 0; mi < 2; mi++)
#pragma unroll
        for (int ni = 0; ni < 8; ni++)
#pragma unroll
            for (int r = 0; r < 4; r++) acc[mi][ni][r] = 0.f;

    LOAD_A(0, 0);
    LOAD_B(0, 0);
    CP_COMMIT();

    for (int kc = 0; kc < chunks; kc++) {
        const int st = kc & 1;
        if (kc + 1 < chunks) {
            LOAD_A(kc + 1, st ^ 1);
            LOAD_B(kc + 1, st ^ 1);
            CP_COMMIT();
            CP_WAIT1();
        } else {
            CP_WAIT0();
        }
        __syncthreads();

        const uint32_t abase = sbase + st * STAGE;
        const uint32_t bbase = abase + 32768;
#pragma unroll
        for (int kk = 0; kk < 4; kk++) {
            int kg = (kc * 4 + kk) * 8 + (lane & 3);
            float fa0 = sa[kg], fc0 = sc[kg];
            float fa4 = sa[kg + 4], fc4 = sc[kg + 4];

            uint32_t ah[2][4], al[2][4];
#pragma unroll
            for (int mi = 0; mi < 2; mi++) {
                int mt = wm * 2 + mi;
                float ar[4];
                lds128f(ar, abase + (uint32_t)((((mt * 4 + kk) * 32 + lane) * 4) * 4));
                float f0 = fmaf(ar[0], fa0, fc0);
                float f1 = fmaf(ar[1], fa0, fc0);
                float f2 = fmaf(ar[2], fa4, fc4);
                float f3 = fmaf(ar[3], fa4, fc4);
                split_tf32(f0, ah[mi][0], al[mi][0]);
                split_tf32(f1, ah[mi][1], al[mi][1]);
                split_tf32(f2, ah[mi][2], al[mi][2]);
                split_tf32(f3, ah[mi][3], al[mi][3]);
            }
#pragma unroll
            for (int h = 0; h < 2; h++) {
                uint32_t bf[4][4];
#pragma unroll
                for (int ni = 0; ni < 4; ni++) {
                    int nt = wn2 * 8 + h * 4 + ni;
                    lds128(bf[ni], bbase + (uint32_t)((((nt * 4 + kk) * 32 + lane) * 4) * 4));
                }
#pragma unroll
                for (int ni = 0; ni < 4; ni++)
#pragma unroll
                    for (int mi = 0; mi < 2; mi++)
                        mma8(acc[mi][h * 4 + ni], ah[mi], bf[ni][0], bf[ni][1]);   // hi*hi
#pragma unroll
                for (int ni = 0; ni < 4; ni++)
#pragma unroll
                    for (int mi = 0; mi < 2; mi++)
                        mma8(acc[mi][h * 4 + ni], al[mi], bf[ni][0], bf[ni][1]);   // lo*hi
#pragma unroll
                for (int ni = 0; ni < 4; ni++)
#pragma unroll
                    for (int mi = 0; mi < 2; mi++)
                        mma8(acc[mi][h * 4 + ni], ah[mi], bf[ni][2], bf[ni][3]);   // hi*lo
            }
        }
        __syncthreads();
    }

    const int r = lane >> 2, q = lane & 3;
    float colacc[8][4];
#pragma unroll
    for (int ni = 0; ni < 8; ni++)
#pragma unroll
        for (int u = 0; u < 4; u++) colacc[ni][u] = 0.f;

#pragma unroll
    for (int mi = 0; mi < 2; mi++) {
        int m = blockIdx.y * 256 + wm * 32 + mi * 16 + r;
#pragma unroll
        for (int ni = 0; ni < 8; ni++) {
            int n = nt0 * 8 + wn2 * 64 + ni * 8 + 2 * q;
            float b0 = __ldg(bias + n), b1 = __ldg(bias + n + 1);
            float v0 = acc[mi][ni][0] + b0;
            float v1 = acc[mi][ni][1] + b1;
            float v2 = acc[mi][ni][2] + b0;
            float v3 = acc[mi][ni][3] + b1;
            if (do_tanh) { v0 = tanhf(v0); v1 = tanhf(v1); v2 = tanhf(v2); v3 = tanhf(v3); }
            colacc[ni][0] += v0 + v2;
            colacc[ni][1] += v1 + v3;
            colacc[ni][2] += v0 * v0 + v2 * v2;
            colacc[ni][3] += v1 * v1 + v3 * v3;
            if (tile_out) {
                int base = ((((m >> 4) * KT_H + (n >> 3)) * 32 + (m & 7) * 4 + (n & 3)) << 2)
                         + 2 * ((n >> 2) & 1);
                *(float2*)(out + base)     = make_float2(v0, v2);
                *(float2*)(out + base + 4) = make_float2(v1, v3);
            } else {
                *(float2*)(out + (size_t)m * ldo + n) = make_float2(v0, v1);
                *(float2*)(out + (size_t)(m + 8) * ldo + n) = make_float2(v2, v3);
            }
        }
    }

    if (csumB != nullptr) {
        float* csum = csumB + (size_t)step * DH;
        float* csq  = csqB + (size_t)step * DH;
        if (tid < 128) { scol[tid] = 0.f; ssq[tid] = 0.f; }
        __syncthreads();
#pragma unroll
        for (int ni = 0; ni < 8; ni++) {
            float a0 = colacc[ni][0], a1 = colacc[ni][1];
            float q0 = colacc[ni][2], q1 = colacc[ni][3];
#pragma unroll
            for (int off = 4; off < 32; off <<= 1) {
                a0 += __shfl_xor_sync(0xffffffffu, a0, off);
                a1 += __shfl_xor_sync(0xffffffffu, a1, off);
                q0 += __shfl_xor_sync(0xffffffffu, q0, off);
                q1 += __shfl_xor_sync(0xffffffffu, q1, off);
            }
            if (r == 0) {
                int cn = wn2 * 64 + ni * 8 + 2 * q;
                atomicAdd(&scol[cn], a0);
                atomicAdd(&scol[cn + 1], a1);
                atomicAdd(&ssq[cn], q0);
                atomicAdd(&ssq[cn + 1], q1);
            }
        }
        __syncthreads();
        if (tid < 128) {
            int col = blockIdx.x * 128 + tid;
            atomicAdd(csum + col, scol[tid]);
            atomicAdd(csq + col, ssq[tid]);
        }
    }
#undef LOAD_A
#undef LOAD_B
}

// ---------------- reductions / scatter / y recursion ----------------
__global__ void s_kernel() {
    int b = blockIdx.x, i = blockIdx.y, d = threadIdx.x;
    float zt = g_zt[((size_t)i * BATCH + b) * DD + d];
    float zd = (i > NDLY) ? g_zt[((size_t)(i - NDLY - 1) * BATCH + b) * DD + d] : 0.f;
    float dw = g_dWT[((size_t)b * NSTEP + i) * DD + d];
    float p1 = zt * zd;
    float p2 = zt * dw;
#pragma unroll
    for (int off = 16; off; off >>= 1) {
        p1 += __shfl_down_sync(0xffffffffu, p1, off);
        p2 += __shfl_down_sync(0xffffffffu, p2, off);
    }
    __shared__ float red[2][4];
    int w = d >> 5, lane = d & 31;
    if (lane == 0) { red[0][w] = p1; red[1][w] = p2; }
    __syncthreads();
    if (d == 0) {
        float s1 = red[0][0] + red[0][1] + red[0][2] + red[0][3];
        float s2 = red[1][0] + red[1][1] + red[1][2] + red[1][3];
        g_C1[i * BATCH + b] = s1 + 0.01f * g_xrow[b * TT + i + NDLY];
        g_S2[i * BATCH + b] = s2;
    }
}

__global__ void zscatter_kernel(float* __restrict__ z) {
    __shared__ float sm[NSTEP][DD + 1];
    int b = blockIdx.x;
    for (int q = threadIdx.x; q < NSTEP * DD; q += 256) {
        int i = q >> 7, d = q & 127;
        sm[i][d] = g_zt[((size_t)i * BATCH + b) * DD + d];
    }
    __syncthreads();
    for (int q = threadIdx.x; q < DD * TT; q += 256) {
        int d = q / TT, t = q - d * TT;
        float v = (t <= NDLY) ? 0.f : sm[t - NDLY - 1][d];
        z[(size_t)b * DD * TT + q] = v;
    }
}

__global__ void yrec_kernel(const float* __restrict__ y0, float* __restrict__ yt,
                            float* __restrict__ y) {
    int b = blockIdx.x * 256 + threadIdx.x;
    if (b >= BATCH) return;
    float y0v = __ldg(y0);
    float ycur = y0v;
    float yh[NSTEP];
    for (int t = 0; t <= NDLY; t++) y[b * TT + t] = y0v;
#pragma unroll 1
    for (int i = 0; i < NSTEP; i++) {
        float yd = (i <= NDLY) ? y0v : yh[i - NDLY - 1];
        float drv = -ycur + 0.1f * yd + g_C1[i * BATCH + b];
        ycur = ycur - drv * DTC + g_S2[i * BATCH + b];
        yh[i] = ycur;
        y[b * TT + NDLY + 1 + i] = ycur;
    }
    yt[b] = ycur;
}

// ---------------- host launch ----------------
static float* sym_addr(const void* sym) {
    void* p = nullptr;
    cudaGetSymbolAddress(&p, sym);
    return (float*)p;
}

extern "C" void kernel_launch(void* const* d_in, const int* in_sizes, int n_in,
                              void* d_out, int out_size) {
    const float* x        = (const float*)d_in[0];
    const float* dW       = (const float*)d_in[1];
    const float* y0       = (const float*)d_in[2];
    const float* bn_in_g  = (const float*)d_in[3];
    const float* bn_in_b  = (const float*)d_in[4];
    const float* W_in     = (const float*)d_in[5];
    const float* b_in     = (const float*)d_in[6];
    const float* Ws_h     = (const float*)d_in[7];
    const float* bs_h     = (const float*)d_in[8];
    const float* bns_g    = (const float*)d_in[9];
    const float* bns_b    = (const float*)d_in[10];
    const float* bn_out_g = (const float*)d_in[11];
    const float* bn_out_b = (const float*)d_in[12];
    const float* W_out    = (const float*)d_in[13];
    const float* b_out    = (const float*)d_in[14];

    float* yt = (float*)d_out;
    float* y  = yt + BATCH;
    float* z  = y + (size_t)BATCH * TT;

    float* bufA = sym_addr(g_bufA);
    float* bufB = sym_addr(g_bufB);
    float* Bsp  = sym_addr(g_Bsp);
    float* zt   = sym_addr(g_zt);
    float* cs   = sym_addr(g_cs);
    float* cq   = sym_addr(g_cq);

    cudaFuncSetAttribute(gemm_mma_kernel, cudaFuncAttributeMaxDynamicSharedMemorySize, GEMM_SMEM);

    mega_setup_kernel<<<R0 + R1 + R2 + R3 + R4 + R5, 256>>>(x, dW, W_in, Ws_h, W_out);
    gather_all_kernel<<<dim3(1152, NSTEP), 256>>>(bn_in_g, bn_in_b);

    dim3 gridH(8, 16, NSTEP);
    dim3 gridO(1, 16, NSTEP);

    // input layer (no fold): bufB -> bufA, stats cs[0]   (chunks = 36/4 = 9)
    gemm_mma_kernel<<<gridH, 512, GEMM_SMEM>>>(bufB, KT_IN, KT_IN / 4, A_IN_STRIDE,
                                               Bsp + BIN_OFF,
                                               nullptr, nullptr, nullptr, nullptr,
                                               b_in, bufA, A_H_STRIDE, 0, 1, 1,
                                               cs + 0 * NSTEP * DH, cq + 0 * NSTEP * DH);
    // hidden 1: bufA -> bufB   (chunks = 128/4 = 32)
    gemm_mma_kernel<<<gridH, 512, GEMM_SMEM>>>(bufA, KT_H, KT_H / 4, A_H_STRIDE,
                                               Bsp + BH_OFF,
                                               cs + 0 * NSTEP * DH, cq + 0 * NSTEP * DH,
                                               bns_g + 0 * DH, bns_b + 0 * DH,
                                               bs_h + 0 * DH, bufB, A_H_STRIDE, 0, 1, 1,
                                               cs + 1 * NSTEP * DH, cq + 1 * NSTEP * DH);
    // hidden 2: bufB -> bufA
    gemm_mma_kernel<<<gridH, 512, GEMM_SMEM>>>(bufB, KT_H, KT_H / 4, A_H_STRIDE,
                                               Bsp + BH_OFF + BH_SZ,
                                               cs + 1 * NSTEP * DH, cq + 1 * NSTEP * DH,
                                               bns_g + 1 * DH, bns_b + 1 * DH,
                                               bs_h + 1 * DH, bufA, A_H_STRIDE, 0, 1, 1,
                                               cs + 2 * NSTEP * DH, cq + 2 * NSTEP * DH);
    // hidden 3: bufA -> bufB
    gemm_mma_kernel<<<gridH, 512, GEMM_SMEM>>>(bufA, KT_H, KT_H / 4, A_H_STRIDE,
                                               Bsp + BH_OFF + 2 * BH_SZ,
                                               cs + 2 * NSTEP * DH, cq + 2 * NSTEP * DH,
                                               bns_g + 2 * DH, bns_b + 2 * DH,
                                               bs_h + 2 * DH, bufB, A_H_STRIDE, 0, 1, 1,
                                               cs + 3 * NSTEP * DH, cq + 3 * NSTEP * DH);
    // output layer: bufB -> zt
    gemm_mma_kernel<<<gridO, 512, GEMM_SMEM>>>(bufB, KT_H, KT_H / 4, A_H_STRIDE,
                                               Bsp + BOUT_OFF,
                                               cs + 3 * NSTEP * DH, cq + 3 * NSTEP * DH,
                                               bn_out_g, bn_out_b,
                                               b_out, zt, ZT_STRIDE, DD, 0, 0,
                                               nullptr, nullptr);

    s_kernel<<<dim3(BATCH, NSTEP), DD>>>();
    zscatter_kernel<<<BATCH, 256>>>(z);
    yrec_kernel<<<(BATCH + 255) / 256, 256>>>(y0, yt, y);
}

// round 15
// speedup vs baseline: 1.1522x; 1.0777x over previous
#include <cuda_runtime.h>
#include <math.h>
#include <stdint.h>

#define BATCH 4096
#define DX 128
#define TT 81
#define DH 1024
#define KIN 257
#define KINP 288
#define DD 128
#define NSTEP 64
#define NDLY 16
#define DTC 0.02f
#define EPSB 1e-5f

#define KT_IN 36
#define KT_H  128

/* B planes: interleaved hi/lo per lane: [ntile][ktile][lane][b0h,b1h,b0l,b1l] */
#define BIN_OFF  0
#define BIN_SZ   (128 * KT_IN * 128)
#define BH_OFF   (BIN_OFF + BIN_SZ)
#define BH_SZ    (128 * KT_H * 128)
#define BOUT_OFF (BH_OFF + 3 * BH_SZ)
#define BOUT_SZ  (16 * KT_H * 128)
#define BSP_TOTAL (BOUT_OFF + BOUT_SZ)

#define STAGE 49152            /* Araw 16K | B 32K (K-chunk = 32, 128-row tile) */
#define GEMM_SMEM (2 * STAGE)

#define A_IN_STRIDE  ((size_t)BATCH * KINP)
#define A_H_STRIDE   ((size_t)BATCH * DH)
#define ZT_STRIDE    ((size_t)BATCH * DD)

// ---------------- device scratch ----------------
__device__ float g_Bsp[BSP_TOTAL];
__device__ float g_bufA[(size_t)NSTEP * BATCH * DH];
__device__ float g_bufB[(size_t)NSTEP * BATCH * DH];
__device__ float g_zt[(size_t)NSTEP * BATCH * DD];
__device__ float g_xT[(size_t)BATCH * TT * DX];
__device__ float g_dWT[(size_t)BATCH * NSTEP * DD];
__device__ float g_xrow[BATCH * TT];
__device__ float g_cs[4 * NSTEP * DH];
__device__ float g_cq[4 * NSTEP * DH];
__device__ float g_xsum[DX * TT];
__device__ float g_xsq[DX * TT];
__device__ float g_C1[NSTEP * BATCH];
__device__ float g_S2[NSTEP * BATCH];

// ---------------- helpers ----------------
__device__ __forceinline__ uint32_t smem_u32(const void* p) {
    uint32_t a;
    asm("{ .reg .u64 t; cvta.to.shared.u64 t, %1; cvt.u32.u64 %0, t; }" : "=r"(a) : "l"(p));
    return a;
}
__device__ __forceinline__ uint32_t tf32_rna(float x) {
    uint32_t u; asm("cvt.rna.tf32.f32 %0, %1;" : "=r"(u) : "f"(x)); return u;
}
__device__ __forceinline__ void split_tf32(float x, uint32_t& h, uint32_t& l) {
    h = tf32_rna(x);
    l = tf32_rna(x - __uint_as_float(h));
}
__device__ __forceinline__ float fast_tanh(float x) {
    float e = __expf(2.f * x);
    return 1.f - __fdividef(2.f, e + 1.f);
}
__device__ __forceinline__ void lds128(uint32_t* r, uint32_t a) {
    asm volatile("ld.shared.v4.b32 {%0,%1,%2,%3}, [%4];"
                 : "=r"(r[0]), "=r"(r[1]), "=r"(r[2]), "=r"(r[3]) : "r"(a));
}
__device__ __forceinline__ void lds128f(float* r, uint32_t a) {
    asm volatile("ld.shared.v4.f32 {%0,%1,%2,%3}, [%4];"
                 : "=f"(r[0]), "=f"(r[1]), "=f"(r[2]), "=f"(r[3]) : "r"(a));
}
__device__ __forceinline__ void cpasync16(uint32_t s, const void* g) {
    asm volatile("cp.async.cg.shared.global [%0], [%1], 16;" :: "r"(s), "l"(g));
}
#define CP_COMMIT() asm volatile("cp.async.commit_group;" ::: "memory")
#define CP_WAIT1()  asm volatile("cp.async.wait_group 1;" ::: "memory")
#define CP_WAIT0()  asm volatile("cp.async.wait_group 0;" ::: "memory")

__device__ __forceinline__ void mma8(float* d, const uint32_t* a, uint32_t b0, uint32_t b1) {
    asm volatile(
        "mma.sync.aligned.m16n8k8.row.col.f32.tf32.tf32.f32 "
        "{%0,%1,%2,%3}, {%4,%5,%6,%7}, {%8,%9}, {%0,%1,%2,%3};"
        : "+f"(d[0]), "+f"(d[1]), "+f"(d[2]), "+f"(d[3])
        : "r"(a[0]), "r"(a[1]), "r"(a[2]), "r"(a[3]), "r"(b0), "r"(b1));
}

// ---------------- mega setup: xstats | zero | xT | dWT | xrow | split_w ----------------
#define R0 (DX * TT)
#define R1 64
#define R2 (BATCH * 12)
#define R3 (BATCH * 8)
#define R4 BATCH
#define R5 13952

__global__ void mega_setup_kernel(const float* __restrict__ x, const float* __restrict__ dW,
                                  const float* __restrict__ W_in, const float* __restrict__ Ws_h,
                                  const float* __restrict__ W_out) {
    int b = blockIdx.x;
    if (b < R0) {
        int d = b / TT, j = b % TT;
        float s = 0.f, q = 0.f;
        const float* base = x + (size_t)d * TT + j;
        for (int r = 0; r < 16; r++) {
            float v = base[(size_t)(threadIdx.x + r * 256) * DX * TT];
            s += v; q += v * v;
        }
#pragma unroll
        for (int off = 16; off; off >>= 1) {
            s += __shfl_down_sync(0xffffffffu, s, off);
            q += __shfl_down_sync(0xffffffffu, q, off);
        }
        __shared__ float rs[8], rq[8];
        int w = threadIdx.x >> 5;
        if ((threadIdx.x & 31) == 0) { rs[w] = s; rq[w] = q; }
        __syncthreads();
        if (threadIdx.x == 0) {
            float a = 0.f, c = 0.f;
#pragma unroll
            for (int u = 0; u < 8; u++) { a += rs[u]; c += rq[u]; }
            g_xsum[d * TT + j] = a;
            g_xsq[d * TT + j] = c;
        }
        return;
    }
    b -= R0;
    if (b < R1) {
        int base = b * (4 * NSTEP * DH / R1);
        for (int i = threadIdx.x; i < 4 * NSTEP * DH / R1; i += 256) {
            g_cs[base + i] = 0.f;
            g_cq[base + i] = 0.f;
        }
        return;
    }
    b -= R1;
    if (b < R2) {
        __shared__ float tile[32][33];
        int bb = b / 12, r = b % 12;
        int ttile = r / 4, ktile = r % 4;
        int lane = threadIdx.x & 31, row4 = threadIdx.x >> 5;
#pragma unroll
        for (int rr = row4; rr < 32; rr += 8) {
            int k = ktile * 32 + rr;
            int t = ttile * 32 + lane;
            tile[rr][lane] = (t < TT) ? x[(size_t)bb * DX * TT + (size_t)k * TT + t] : 0.f;
        }
        __syncthreads();
#pragma unroll
        for (int rr = row4; rr < 32; rr += 8) {
            int t = ttile * 32 + rr;
            int k = ktile * 32 + lane;
            if (t < TT) g_xT[(size_t)bb * TT * DX + (size_t)t * DX + k] = tile[lane][rr];
        }
        return;
    }
    b -= R2;
    if (b < R3) {
        __shared__ float tile[32][33];
        int bb = b / 8, r = b % 8;
        int itile = r / 4, dtile = r % 4;
        int lane = threadIdx.x & 31, row4 = threadIdx.x >> 5;
#pragma unroll
        for (int rr = row4; rr < 32; rr += 8) {
            int dcol = dtile * 32 + rr;
            int i = itile * 32 + lane;
            tile[rr][lane] = dW[(size_t)bb * DD * NSTEP + (size_t)dcol * NSTEP + i];
        }
        __syncthreads();
#pragma unroll
        for (int rr = row4; rr < 32; rr += 8) {
            int i = itile * 32 + rr;
            int dcol = dtile * 32 + lane;
            g_dWT[(size_t)bb * NSTEP * DD + (size_t)i * DD + dcol] = tile[lane][rr];
        }
        return;
    }
    b -= R3;
    if (b < R4) {
        int t = threadIdx.x;
        if (t < TT) {
            float s = 0.f;
            const float* base = x + (size_t)b * DX * TT + t;
            for (int d = 0; d < DX; d++) s += base[(size_t)d * TT];
            g_xrow[b * TT + t] = s;
        }
        return;
    }
    b -= R4;
    {
        size_t i = (size_t)b * 256 + threadIdx.x;
        const size_t N_IN = (size_t)KINP * DH;
        const size_t N_H  = (size_t)DH * DH;
        const size_t N_O  = (size_t)DH * DD;
        if (i >= N_IN + 3 * N_H + N_O) return;
        int k, n, Kt; size_t base; float v;
        if (i < N_IN) {
            k = (int)(i / DH); n = (int)(i % DH);
            v = (k < KIN) ? W_in[(size_t)k * DH + n] : 0.f;
            Kt = KT_IN; base = BIN_OFF;
        } else if (i < N_IN + 3 * N_H) {
            size_t j = i - N_IN;
            int l = (int)(j / N_H); size_t r = j % N_H;
            k = (int)(r / DH); n = (int)(r % DH);
            v = Ws_h[(size_t)l * N_H + (size_t)k * DH + n];
            Kt = KT_H; base = BH_OFF + (size_t)l * BH_SZ;
        } else {
            size_t j = i - N_IN - 3 * N_H;
            k = (int)(j / DD); n = (int)(j % DD);
            v = W_out[(size_t)k * DD + n];
            Kt = KT_H; base = BOUT_OFF;
        }
        uint32_t h, l2;
        split_tf32(v, h, l2);
        int nt = n >> 3, kt = k >> 3;
        int lane = (n & 7) * 4 + (k & 3);
        int w = (k & 7) >> 2;
        size_t off = base + ((size_t)(nt * Kt + kt) * 32 + lane) * 4;
        g_Bsp[off + w]     = __uint_as_float(h);
        g_Bsp[off + w + 2] = __uint_as_float(l2);
    }
}

// ---------------- gather all steps (inline input-BN fold) -> raw t0 tiles ----------------
__global__ void gather_all_kernel(const float* __restrict__ gg, const float* __restrict__ bb) {
    int i = blockIdx.y;
    int it = i + NDLY;
    int idx = blockIdx.x * 256 + threadIdx.x;
    int lane = idx & 31;
    int t2 = idx >> 5;
    int kt = t2 % KT_IN, mt = t2 / KT_IN;
    int m0 = mt * 16 + (lane >> 2);
    int k0 = kt * 8 + (lane & 3);

    float av[2], cv[2];
#pragma unroll
    for (int h = 0; h < 2; h++) {
        int k = k0 + h * 4;
        float a = 0.f, c = 0.f;
        if (k < 2 * DX) {
            int d  = (k < DX) ? k  : k - DX;
            int tt = (k < DX) ? it : i;
            float s = __ldg(g_xsum + d * TT + tt), qq = __ldg(g_xsq + d * TT + tt);
            float m = s * (1.f / BATCH);
            float v = qq * (1.f / BATCH) - m * m;
            if (v < 0.f) v = 0.f;
            a = __ldg(gg + k) * rsqrtf(v + EPSB);
            c = __ldg(bb + k) - m * a;
        } else if (k == 2 * DX) {
            c = __ldg(bb + k);
        }
        av[h] = a; cv[h] = c;
    }

    const float* xr0 = g_xT + (size_t)m0 * TT * DX;
    const float* xr8 = g_xT + (size_t)(m0 + 8) * TT * DX;
    int k4 = k0 + 4;
    float r0 = 0.f, r1 = 0.f, r2 = 0.f, r3 = 0.f;
    if (k0 < DX)          { r0 = xr0[(size_t)it * DX + k0];       r1 = xr8[(size_t)it * DX + k0]; }
    else if (k0 < 2 * DX) { r0 = xr0[(size_t)i * DX + (k0 - DX)]; r1 = xr8[(size_t)i * DX + (k0 - DX)]; }
    if (k4 < DX)          { r2 = xr0[(size_t)it * DX + k4];       r3 = xr8[(size_t)it * DX + k4]; }
    else if (k4 < 2 * DX) { r2 = xr0[(size_t)i * DX + (k4 - DX)]; r3 = xr8[(size_t)i * DX + (k4 - DX)]; }

    float4 f;
    f.x = fmaf(r0, av[0], cv[0]);
    f.y = fmaf(r1, av[0], cv[0]);
    f.z = fmaf(r2, av[1], cv[1]);
    f.w = fmaf(r3, av[1], cv[1]);
    float* t0 = g_bufB + (size_t)i * A_IN_STRIDE;
    *(float4*)(t0 + ((size_t)(mt * KT_IN + kt) * 32 + lane) * 4) = f;
}

// ---------------- 3xTF32 GEMM: 128x128 CTA (256 thr, 4m x 2n warps), 2 CTAs/SM ----------------
__global__ __launch_bounds__(256, 2)
void gemm_mma_kernel(const float* __restrict__ ApBase, int Kt, int chunks, size_t aStride,
                     const float* __restrict__ Bp,
                     const float* __restrict__ csPB, const float* __restrict__ cqPB,
                     const float* __restrict__ gg, const float* __restrict__ bb,
                     const float* __restrict__ bias,
                     float* __restrict__ outBase, size_t oStride, int ldo, int tile_out, int do_tanh,
                     float* __restrict__ csumB, float* __restrict__ csqB) {
    extern __shared__ float smf[];
    __shared__ float sa[DH], sc[DH];
    __shared__ float scol[128], ssq[128];
    const uint32_t sbase = smem_u32(smf);
    const int tid = threadIdx.x;
    const int step = blockIdx.z;
    const int mt0 = blockIdx.y * 8;      // 8 mtiles = 128 rows per CTA
    const int nt0 = blockIdx.x * 16;     // 16 ntiles = 128 cols per CTA
    const int w = tid >> 5, lane = tid & 31;
    const int wm = w & 3, wn2 = w >> 2;
    const bool fold = (csPB != nullptr);

    const float* Ap = ApBase + (size_t)step * aStride;
    float* out = outBase + (size_t)step * oStride;

    if (fold) {
        const float* csP = csPB + (size_t)step * DH;
        const float* cqP = cqPB + (size_t)step * DH;
        for (int k = tid; k < Kt * 8; k += 256) {
            float m = __ldg(csP + k) * (1.f / BATCH);
            float v = __ldg(cqP + k) * (1.f / BATCH) - m * m;
            if (v < 0.f) v = 0.f;
            float a = __ldg(gg + k) * rsqrtf(v + EPSB);
            sa[k] = a;
            sc[k] = __ldg(bb + k) - m * a;
        }
    } else {
        for (int k = tid; k < Kt * 8; k += 256) { sa[k] = 1.f; sc[k] = 0.f; }
    }
    __syncthreads();

    // stage: A [mt(8)][kt(4)][lane][4] = 16KB | B [nt(16)][kt(4)][lane][4w] = 32KB
#define LOAD_A(kc_, st_)                                                         \
    {                                                                            \
        uint32_t base_ = sbase + (st_) * STAGE;                                  \
        _Pragma("unroll")                                                        \
        for (int i_ = 0; i_ < 4; i_++) {                                         \
            int idx_ = i_ * 256 + tid;                                           \
            int mt_ = idx_ >> 7, kt_ = (idx_ >> 5) & 3, ln_ = idx_ & 31;         \
            const float* src_ = Ap + (((size_t)(mt0 + mt_) * Kt + (kc_) * 4 + kt_) * 32 + ln_) * 4; \
            cpasync16(base_ + (uint32_t)((((mt_ * 4 + kt_) * 32 + ln_) * 4) * 4), src_); \
        }                                                                        \
    }
#define LOAD_B(kc_, st_)                                                         \
    {                                                                            \
        uint32_t bb_ = sbase + (st_) * STAGE + 16384;                            \
        _Pragma("unroll")                                                        \
        for (int i_ = 0; i_ < 8; i_++) {                                         \
            int idx_ = i_ * 256 + tid;                                           \
            int nt_ = idx_ >> 7, kt_ = (idx_ >> 5) & 3, ln_ = idx_ & 31;         \
            const float* src_ = Bp + ((size_t)(nt0 + nt_) * Kt + (kc_) * 4 + kt_) * 128 + ln_ * 4; \
            cpasync16(bb_ + (uint32_t)((((nt_ * 4 + kt_) * 32 + ln_) * 4) * 4), src_); \
        }                                                                        \
    }

    float acc[2][8][4];
#pragma unroll
    for (int mi = 0; mi < 2; mi++)
#pragma unroll
        for (int ni = 0; ni < 8; ni++)
#pragma unroll
            for (int r = 0; r < 4; r++) acc[mi][ni][r] = 0.f;

    LOAD_A(0, 0);
    LOAD_B(0, 0);
    CP_COMMIT();

    for (int kc = 0; kc < chunks; kc++) {
        const int st = kc & 1;
        if (kc + 1 < chunks) {
            LOAD_A(kc + 1, st ^ 1);
            LOAD_B(kc + 1, st ^ 1);
            CP_COMMIT();
            CP_WAIT1();
        } else {
            CP_WAIT0();
        }
        __syncthreads();

        const uint32_t abase = sbase + st * STAGE;
        const uint32_t bbase = abase + 16384;
#pragma unroll
        for (int kk = 0; kk < 4; kk++) {
            int kg = (kc * 4 + kk) * 8 + (lane & 3);
            float fa0 = sa[kg], fc0 = sc[kg];
            float fa4 = sa[kg + 4], fc4 = sc[kg + 4];

            uint32_t ah[2][4], al[2][4];
#pragma unroll
            for (int mi = 0; mi < 2; mi++) {
                int mt = wm * 2 + mi;
                float ar[4];
                lds128f(ar, abase + (uint32_t)((((mt * 4 + kk) * 32 + lane) * 4) * 4));
                float f0 = fmaf(ar[0], fa0, fc0);
                float f1 = fmaf(ar[1], fa0, fc0);
                float f2 = fmaf(ar[2], fa4, fc4);
                float f3 = fmaf(ar[3], fa4, fc4);
                split_tf32(f0, ah[mi][0], al[mi][0]);
                split_tf32(f1, ah[mi][1], al[mi][1]);
                split_tf32(f2, ah[mi][2], al[mi][2]);
                split_tf32(f3, ah[mi][3], al[mi][3]);
            }
#pragma unroll
            for (int h = 0; h < 2; h++) {
                uint32_t bf[4][4];
#pragma unroll
                for (int ni = 0; ni < 4; ni++) {
                    int nt = wn2 * 8 + h * 4 + ni;
                    lds128(bf[ni], bbase + (uint32_t)((((nt * 4 + kk) * 32 + lane) * 4) * 4));
                }
#pragma unroll
                for (int ni = 0; ni < 4; ni++)
#pragma unroll
                    for (int mi = 0; mi < 2; mi++)
                        mma8(acc[mi][h * 4 + ni], ah[mi], bf[ni][0], bf[ni][1]);   // hi*hi
#pragma unroll
                for (int ni = 0; ni < 4; ni++)
#pragma unroll
                    for (int mi = 0; mi < 2; mi++)
                        mma8(acc[mi][h * 4 + ni], al[mi], bf[ni][0], bf[ni][1]);   // lo*hi
#pragma unroll
                for (int ni = 0; ni < 4; ni++)
#pragma unroll
                    for (int mi = 0; mi < 2; mi++)
                        mma8(acc[mi][h * 4 + ni], ah[mi], bf[ni][2], bf[ni][3]);   // hi*lo
            }
        }
        __syncthreads();
    }

    const int r = lane >> 2, q = lane & 3;
    float colacc[8][4];
#pragma unroll
    for (int ni = 0; ni < 8; ni++)
#pragma unroll
        for (int u = 0; u < 4; u++) colacc[ni][u] = 0.f;

#pragma unroll
    for (int mi = 0; mi < 2; mi++) {
        int m = blockIdx.y * 128 + wm * 32 + mi * 16 + r;
#pragma unroll
        for (int ni = 0; ni < 8; ni++) {
            int n = nt0 * 8 + wn2 * 64 + ni * 8 + 2 * q;
            float b0 = __ldg(bias + n), b1 = __ldg(bias + n + 1);
            float v0 = acc[mi][ni][0] + b0;
            float v1 = acc[mi][ni][1] + b1;
            float v2 = acc[mi][ni][2] + b0;
            float v3 = acc[mi][ni][3] + b1;
            if (do_tanh) {
                v0 = fast_tanh(v0); v1 = fast_tanh(v1);
                v2 = fast_tanh(v2); v3 = fast_tanh(v3);
            }
            colacc[ni][0] += v0 + v2;
            colacc[ni][1] += v1 + v3;
            colacc[ni][2] += v0 * v0 + v2 * v2;
            colacc[ni][3] += v1 * v1 + v3 * v3;
            if (tile_out) {
                int base = ((((m >> 4) * KT_H + (n >> 3)) * 32 + (m & 7) * 4 + (n & 3)) << 2)
                         + 2 * ((n >> 2) & 1);
                *(float2*)(out + base)     = make_float2(v0, v2);
                *(float2*)(out + base + 4) = make_float2(v1, v3);
            } else {
                *(float2*)(out + (size_t)m * ldo + n) = make_float2(v0, v1);
                *(float2*)(out + (size_t)(m + 8) * ldo + n) = make_float2(v2, v3);
            }
        }
    }

    if (csumB != nullptr) {
        float* csum = csumB + (size_t)step * DH;
        float* csq  = csqB + (size_t)step * DH;
        if (tid < 128) { scol[tid] = 0.f; ssq[tid] = 0.f; }
        __syncthreads();
#pragma unroll
        for (int ni = 0; ni < 8; ni++) {
            float a0 = colacc[ni][0], a1 = colacc[ni][1];
            float q0 = colacc[ni][2], q1 = colacc[ni][3];
#pragma unroll
            for (int off = 4; off < 32; off <<= 1) {
                a0 += __shfl_xor_sync(0xffffffffu, a0, off);
                a1 += __shfl_xor_sync(0xffffffffu, a1, off);
                q0 += __shfl_xor_sync(0xffffffffu, q0, off);
                q1 += __shfl_xor_sync(0xffffffffu, q1, off);
            }
            if (r == 0) {
                int cn = wn2 * 64 + ni * 8 + 2 * q;
                atomicAdd(&scol[cn], a0);
                atomicAdd(&scol[cn + 1], a1);
                atomicAdd(&ssq[cn], q0);
                atomicAdd(&ssq[cn + 1], q1);
            }
        }
        __syncthreads();
        if (tid < 128) {
            int col = blockIdx.x * 128 + tid;
            atomicAdd(csum + col, scol[tid]);
            atomicAdd(csq + col, ssq[tid]);
        }
    }
#undef LOAD_A
#undef LOAD_B
}

// ---------------- reductions / scatter / y recursion ----------------
__global__ void s_kernel() {
    int b = blockIdx.x, i = blockIdx.y, d = threadIdx.x;
    float zt = g_zt[((size_t)i * BATCH + b) * DD + d];
    float zd = (i > NDLY) ? g_zt[((size_t)(i - NDLY - 1) * BATCH + b) * DD + d] : 0.f;
    float dw = g_dWT[((size_t)b * NSTEP + i) * DD + d];
    float p1 = zt * zd;
    float p2 = zt * dw;
#pragma unroll
    for (int off = 16; off; off >>= 1) {
        p1 += __shfl_down_sync(0xffffffffu, p1, off);
        p2 += __shfl_down_sync(0xffffffffu, p2, off);
    }
    __shared__ float red[2][4];
    int w = d >> 5, lane = d & 31;
    if (lane == 0) { red[0][w] = p1; red[1][w] = p2; }
    __syncthreads();
    if (d == 0) {
        float s1 = red[0][0] + red[0][1] + red[0][2] + red[0][3];
        float s2 = red[1][0] + red[1][1] + red[1][2] + red[1][3];
        g_C1[i * BATCH + b] = s1 + 0.01f * g_xrow[b * TT + i + NDLY];
        g_S2[i * BATCH + b] = s2;
    }
}

__global__ void zscatter_kernel(float* __restrict__ z) {
    __shared__ float sm[NSTEP][DD + 1];
    int b = blockIdx.x;
    for (int q = threadIdx.x; q < NSTEP * DD; q += 256) {
        int i = q >> 7, d = q & 127;
        sm[i][d] = g_zt[((size_t)i * BATCH + b) * DD + d];
    }
    __syncthreads();
    for (int q = threadIdx.x; q < DD * TT; q += 256) {
        int d = q / TT, t = q - d * TT;
        float v = (t <= NDLY) ? 0.f : sm[t - NDLY - 1][d];
        z[(size_t)b * DD * TT + q] = v;
    }
}

__global__ void yrec_kernel(const float* __restrict__ y0, float* __restrict__ yt,
                            float* __restrict__ y) {
    int b = blockIdx.x * 256 + threadIdx.x;
    if (b >= BATCH) return;
    float y0v = __ldg(y0);
    float ycur = y0v;
    float yh[NSTEP];
    for (int t = 0; t <= NDLY; t++) y[b * TT + t] = y0v;
#pragma unroll 1
    for (int i = 0; i < NSTEP; i++) {
        float yd = (i <= NDLY) ? y0v : yh[i - NDLY - 1];
        float drv = -ycur + 0.1f * yd + g_C1[i * BATCH + b];
        ycur = ycur - drv * DTC + g_S2[i * BATCH + b];
        yh[i] = ycur;
        y[b * TT + NDLY + 1 + i] = ycur;
    }
    yt[b] = ycur;
}

// ---------------- host launch ----------------
static float* sym_addr(const void* sym) {
    void* p = nullptr;
    cudaGetSymbolAddress(&p, sym);
    return (float*)p;
}

extern "C" void kernel_launch(void* const* d_in, const int* in_sizes, int n_in,
                              void* d_out, int out_size) {
    const float* x        = (const float*)d_in[0];
    const float* dW       = (const float*)d_in[1];
    const float* y0       = (const float*)d_in[2];
    const float* bn_in_g  = (const float*)d_in[3];
    const float* bn_in_b  = (const float*)d_in[4];
    const float* W_in     = (const float*)d_in[5];
    const float* b_in     = (const float*)d_in[6];
    const float* Ws_h     = (const float*)d_in[7];
    const float* bs_h     = (const float*)d_in[8];
    const float* bns_g    = (const float*)d_in[9];
    const float* bns_b    = (const float*)d_in[10];
    const float* bn_out_g = (const float*)d_in[11];
    const float* bn_out_b = (const float*)d_in[12];
    const float* W_out    = (const float*)d_in[13];
    const float* b_out    = (const float*)d_in[14];

    float* yt = (float*)d_out;
    float* y  = yt + BATCH;
    float* z  = y + (size_t)BATCH * TT;

    float* bufA = sym_addr(g_bufA);
    float* bufB = sym_addr(g_bufB);
    float* Bsp  = sym_addr(g_Bsp);
    float* zt   = sym_addr(g_zt);
    float* cs   = sym_addr(g_cs);
    float* cq   = sym_addr(g_cq);

    cudaFuncSetAttribute(gemm_mma_kernel, cudaFuncAttributeMaxDynamicSharedMemorySize, GEMM_SMEM);

    mega_setup_kernel<<<R0 + R1 + R2 + R3 + R4 + R5, 256>>>(x, dW, W_in, Ws_h, W_out);
    gather_all_kernel<<<dim3(1152, NSTEP), 256>>>(bn_in_g, bn_in_b);

    dim3 gridH(8, 32, NSTEP);   // 128x128 tiles: 8 n-blocks, 32 m-blocks
    dim3 gridO(1, 32, NSTEP);

    // input layer (no fold): bufB -> bufA, stats cs[0]   (chunks = 36/4 = 9)
    gemm_mma_kernel<<<gridH, 256, GEMM_SMEM>>>(bufB, KT_IN, KT_IN / 4, A_IN_STRIDE,
                                               Bsp + BIN_OFF,
                                               nullptr, nullptr, nullptr, nullptr,
                                               b_in, bufA, A_H_STRIDE, 0, 1, 1,
                                               cs + 0 * NSTEP * DH, cq + 0 * NSTEP * DH);
    // hidden 1: bufA -> bufB   (chunks = 128/4 = 32)
    gemm_mma_kernel<<<gridH, 256, GEMM_SMEM>>>(bufA, KT_H, KT_H / 4, A_H_STRIDE,
                                               Bsp + BH_OFF,
                                               cs + 0 * NSTEP * DH, cq + 0 * NSTEP * DH,
                                               bns_g + 0 * DH, bns_b + 0 * DH,
                                               bs_h + 0 * DH, bufB, A_H_STRIDE, 0, 1, 1,
                                               cs + 1 * NSTEP * DH, cq + 1 * NSTEP * DH);
    // hidden 2: bufB -> bufA
    gemm_mma_kernel<<<gridH, 256, GEMM_SMEM>>>(bufB, KT_H, KT_H / 4, A_H_STRIDE,
                                               Bsp + BH_OFF + BH_SZ,
                                               cs + 1 * NSTEP * DH, cq + 1 * NSTEP * DH,
                                               bns_g + 1 * DH, bns_b + 1 * DH,
                                               bs_h + 1 * DH, bufA, A_H_STRIDE, 0, 1, 1,
                                               cs + 2 * NSTEP * DH, cq + 2 * NSTEP * DH);
    // hidden 3: bufA -> bufB
    gemm_mma_kernel<<<gridH, 256, GEMM_SMEM>>>(bufA, KT_H, KT_H / 4, A_H_STRIDE,
                                               Bsp + BH_OFF + 2 * BH_SZ,
                                               cs + 2 * NSTEP * DH, cq + 2 * NSTEP * DH,
                                               bns_g + 2 * DH, bns_b + 2 * DH,
                                               bs_h + 2 * DH, bufB, A_H_STRIDE, 0, 1, 1,
                                               cs + 3 * NSTEP * DH, cq + 3 * NSTEP * DH);
    // output layer: bufB -> zt
    gemm_mma_kernel<<<gridO, 256, GEMM_SMEM>>>(bufB, KT_H, KT_H / 4, A_H_STRIDE,
                                               Bsp + BOUT_OFF,
                                               cs + 3 * NSTEP * DH, cq + 3 * NSTEP * DH,
                                               bn_out_g, bn_out_b,
                                               b_out, zt, ZT_STRIDE, DD, 0, 0,
                                               nullptr, nullptr);

    s_kernel<<<dim3(BATCH, NSTEP), DD>>>();
    zscatter_kernel<<<BATCH, 256>>>(z);
    yrec_kernel<<<(BATCH + 255) / 256, 256>>>(y0, yt, y);
}

// round 16
// speedup vs baseline: 1.9034x; 1.6520x over previous
#include <cuda_runtime.h>
#include <math.h>
#include <stdint.h>

#define BATCH 4096
#define DX 128
#define TT 81
#define DH 1024
#define KIN 257
#define KINP 288
#define DD 128
#define NSTEP 64
#define NDLY 16
#define DTC 0.02f
#define EPSB 1e-5f

#define KT16_IN 18      /* 288/16  */
#define KT16_H  64      /* 1024/16 */

/* B: bf16 split, [ntile8][kt16][lane][4 words: b0h,b1h,b0l,b1l] */
#define BIN_OFF  0
#define BIN_SZ   (128 * KT16_IN * 32 * 4)
#define BH_OFF   (BIN_OFF + BIN_SZ)
#define BH_SZ    (128 * KT16_H * 32 * 4)
#define BOUT_OFF (BH_OFF + 3 * BH_SZ)
#define BOUT_SZ  (16 * KT16_H * 32 * 4)
#define BSP_TOTAL (BOUT_OFF + BOUT_SZ)

#define STAGE 32768            /* Araw 16K | B(bf16) 16K, K-chunk 32 */
#define GEMM_SMEM (2 * STAGE)

#define A_IN_STRIDE  ((size_t)BATCH * KINP)
#define A_H_STRIDE   ((size_t)BATCH * DH)
#define ZT_STRIDE    ((size_t)BATCH * DD)

// ---------------- device scratch ----------------
__device__ uint32_t g_Bsp[BSP_TOTAL];
__device__ float g_bufA[(size_t)NSTEP * BATCH * DH];
__device__ float g_bufB[(size_t)NSTEP * BATCH * DH];
__device__ float g_zt[(size_t)NSTEP * BATCH * DD];
__device__ float g_xT[(size_t)BATCH * TT * DX];
__device__ float g_dWT[(size_t)BATCH * NSTEP * DD];
__device__ float g_xrow[BATCH * TT];
__device__ float g_cs[4 * NSTEP * DH];
__device__ float g_cq[4 * NSTEP * DH];
__device__ float g_xsum[DX * TT];
__device__ float g_xsq[DX * TT];
__device__ float g_C1[NSTEP * BATCH];
__device__ float g_S2[NSTEP * BATCH];

// ---------------- helpers ----------------
__device__ __forceinline__ uint32_t smem_u32(const void* p) {
    uint32_t a;
    asm("{ .reg .u64 t; cvta.to.shared.u64 t, %1; cvt.u32.u64 %0, t; }" : "=r"(a) : "l"(p));
    return a;
}
__device__ __forceinline__ uint32_t packbf2(float hi, float lo) {
    uint32_t d;
    asm("cvt.rn.bf16x2.f32 %0, %1, %2;" : "=r"(d) : "f"(hi), "f"(lo));
    return d;
}
// split pair (f0 -> low half, f1 -> high half): hi word + residual-lo word
__device__ __forceinline__ void split_pair(float f0, float f1, uint32_t& h, uint32_t& l) {
    h = packbf2(f1, f0);
    float h0 = __uint_as_float(h << 16);
    float h1 = __uint_as_float(h & 0xffff0000u);
    l = packbf2(f1 - h1, f0 - h0);
}
__device__ __forceinline__ float fast_tanh(float x) {
    float e = __expf(2.f * x);
    return 1.f - __fdividef(2.f, e + 1.f);
}
__device__ __forceinline__ void lds128(uint32_t* r, uint32_t a) {
    asm volatile("ld.shared.v4.b32 {%0,%1,%2,%3}, [%4];"
                 : "=r"(r[0]), "=r"(r[1]), "=r"(r[2]), "=r"(r[3]) : "r"(a));
}
__device__ __forceinline__ void lds128f(float* r, uint32_t a) {
    asm volatile("ld.shared.v4.f32 {%0,%1,%2,%3}, [%4];"
                 : "=f"(r[0]), "=f"(r[1]), "=f"(r[2]), "=f"(r[3]) : "r"(a));
}
__device__ __forceinline__ void cpasync16(uint32_t s, const void* g) {
    asm volatile("cp.async.cg.shared.global [%0], [%1], 16;" :: "r"(s), "l"(g));
}
#define CP_COMMIT() asm volatile("cp.async.commit_group;" ::: "memory")
#define CP_WAIT1()  asm volatile("cp.async.wait_group 1;" ::: "memory")
#define CP_WAIT0()  asm volatile("cp.async.wait_group 0;" ::: "memory")

__device__ __forceinline__ void mma16(float* d, const uint32_t* a, uint32_t b0, uint32_t b1) {
    asm volatile(
        "mma.sync.aligned.m16n8k16.row.col.f32.bf16.bf16.f32 "
        "{%0,%1,%2,%3}, {%4,%5,%6,%7}, {%8,%9}, {%0,%1,%2,%3};"
        : "+f"(d[0]), "+f"(d[1]), "+f"(d[2]), "+f"(d[3])
        : "r"(a[0]), "r"(a[1]), "r"(a[2]), "r"(a[3]), "r"(b0), "r"(b1));
}

// ---------------- mega setup: xstats | zero | xT | dWT | xrow | split_w ----------------
#define R0 (DX * TT)
#define R1 64
#define R2 (BATCH * 12)
#define R3 (BATCH * 8)
#define R4 BATCH
#define R5 13952

__global__ void mega_setup_kernel(const float* __restrict__ x, const float* __restrict__ dW,
                                  const float* __restrict__ W_in, const float* __restrict__ Ws_h,
                                  const float* __restrict__ W_out) {
    int b = blockIdx.x;
    if (b < R0) {
        int d = b / TT, j = b % TT;
        float s = 0.f, q = 0.f;
        const float* base = x + (size_t)d * TT + j;
        for (int r = 0; r < 16; r++) {
            float v = base[(size_t)(threadIdx.x + r * 256) * DX * TT];
            s += v; q += v * v;
        }
#pragma unroll
        for (int off = 16; off; off >>= 1) {
            s += __shfl_down_sync(0xffffffffu, s, off);
            q += __shfl_down_sync(0xffffffffu, q, off);
        }
        __shared__ float rs[8], rq[8];
        int w = threadIdx.x >> 5;
        if ((threadIdx.x & 31) == 0) { rs[w] = s; rq[w] = q; }
        __syncthreads();
        if (threadIdx.x == 0) {
            float a = 0.f, c = 0.f;
#pragma unroll
            for (int u = 0; u < 8; u++) { a += rs[u]; c += rq[u]; }
            g_xsum[d * TT + j] = a;
            g_xsq[d * TT + j] = c;
        }
        return;
    }
    b -= R0;
    if (b < R1) {
        int base = b * (4 * NSTEP * DH / R1);
        for (int i = threadIdx.x; i < 4 * NSTEP * DH / R1; i += 256) {
            g_cs[base + i] = 0.f;
            g_cq[base + i] = 0.f;
        }
        return;
    }
    b -= R1;
    if (b < R2) {
        __shared__ float tile[32][33];
        int bb = b / 12, r = b % 12;
        int ttile = r / 4, ktile = r % 4;
        int lane = threadIdx.x & 31, row4 = threadIdx.x >> 5;
#pragma unroll
        for (int rr = row4; rr < 32; rr += 8) {
            int k = ktile * 32 + rr;
            int t = ttile * 32 + lane;
            tile[rr][lane] = (t < TT) ? x[(size_t)bb * DX * TT + (size_t)k * TT + t] : 0.f;
        }
        __syncthreads();
#pragma unroll
        for (int rr = row4; rr < 32; rr += 8) {
            int t = ttile * 32 + rr;
            int k = ktile * 32 + lane;
            if (t < TT) g_xT[(size_t)bb * TT * DX + (size_t)t * DX + k] = tile[lane][rr];
        }
        return;
    }
    b -= R2;
    if (b < R3) {
        __shared__ float tile[32][33];
        int bb = b / 8, r = b % 8;
        int itile = r / 4, dtile = r % 4;
        int lane = threadIdx.x & 31, row4 = threadIdx.x >> 5;
#pragma unroll
        for (int rr = row4; rr < 32; rr += 8) {
            int dcol = dtile * 32 + rr;
            int i = itile * 32 + lane;
            tile[rr][lane] = dW[(size_t)bb * DD * NSTEP + (size_t)dcol * NSTEP + i];
        }
        __syncthreads();
#pragma unroll
        for (int rr = row4; rr < 32; rr += 8) {
            int i = itile * 32 + rr;
            int dcol = dtile * 32 + lane;
            g_dWT[(size_t)bb * NSTEP * DD + (size_t)i * DD + dcol] = tile[lane][rr];
        }
        return;
    }
    b -= R3;
    if (b < R4) {
        int t = threadIdx.x;
        if (t < TT) {
            float s = 0.f;
            const float* base = x + (size_t)b * DX * TT + t;
            for (int d = 0; d < DX; d++) s += base[(size_t)d * TT];
            g_xrow[b * TT + t] = s;
        }
        return;
    }
    b -= R4;
    {
        size_t i = (size_t)b * 256 + threadIdx.x;
        const size_t N_IN = (size_t)KINP * DH;
        const size_t N_H  = (size_t)DH * DH;
        const size_t N_O  = (size_t)DH * DD;
        if (i >= N_IN + 3 * N_H + N_O) return;
        int k, n, Kt; size_t base; float v;
        if (i < N_IN) {
            k = (int)(i / DH); n = (int)(i % DH);
            v = (k < KIN) ? W_in[(size_t)k * DH + n] : 0.f;
            Kt = KT16_IN; base = BIN_OFF;
        } else if (i < N_IN + 3 * N_H) {
            size_t j = i - N_IN;
            int l = (int)(j / N_H); size_t r = j % N_H;
            k = (int)(r / DH); n = (int)(r % DH);
            v = Ws_h[(size_t)l * N_H + (size_t)k * DH + n];
            Kt = KT16_H; base = BH_OFF + (size_t)l * BH_SZ;
        } else {
            size_t j = i - N_IN - 3 * N_H;
            k = (int)(j / DD); n = (int)(j % DD);
            v = W_out[(size_t)k * DD + n];
            Kt = KT16_H; base = BOUT_OFF;
        }
        uint16_t hh, lh;
        asm("cvt.rn.bf16.f32 %0, %1;" : "=h"(hh) : "f"(v));
        float hf = __uint_as_float((uint32_t)hh << 16);
        asm("cvt.rn.bf16.f32 %0, %1;" : "=h"(lh) : "f"(v - hf));
        int nt = n >> 3, kt = k >> 4, kk = k & 15;
        int reg = kk >> 3;              // 0: k%16 in [0,8), 1: [8,16)
        int q = (kk & 7) >> 1;
        int half = kk & 1;
        int lane = (n & 7) * 4 + q;
        size_t word = base + ((size_t)(nt * Kt + kt) * 32 + lane) * 4;
        uint16_t* B16 = (uint16_t*)g_Bsp;
        B16[(word + reg) * 2 + half]     = hh;   // hi plane words 0,1
        B16[(word + reg + 2) * 2 + half] = lh;   // lo plane words 2,3
    }
}

// ---------------- gather all steps (inline input-BN fold) -> raw A tiles ----------------
// A layout: [mt16][kt16][lane(32)][8 floats: (r,2q),(r,2q+1),(r+8,2q),(r+8,2q+1), +8k x4]
__global__ void gather_all_kernel(const float* __restrict__ gg, const float* __restrict__ bb) {
    int i = blockIdx.y;
    int it = i + NDLY;
    int idx = blockIdx.x * 256 + threadIdx.x;       // 256mt? -> 256*18*32 / 256 = 576 blocks
    int lane = idx & 31;
    int t2 = idx >> 5;
    int kt = t2 % KT16_IN, mt = t2 / KT16_IN;
    int r = lane >> 2, q = lane & 3;
    int m0 = mt * 16 + r;
    int kb = kt * 16 + 2 * q;

    float av[4], cv[4];
#pragma unroll
    for (int h = 0; h < 4; h++) {
        int k = kb + (h >> 1) * 8 + (h & 1);        // 2q, 2q+1, 2q+8, 2q+9
        float a = 0.f, c = 0.f;
        if (k < 2 * DX) {
            int d  = (k < DX) ? k  : k - DX;
            int tt = (k < DX) ? it : i;
            float s = __ldg(g_xsum + d * TT + tt), qq = __ldg(g_xsq + d * TT + tt);
            float m = s * (1.f / BATCH);
            float v = qq * (1.f / BATCH) - m * m;
            if (v < 0.f) v = 0.f;
            a = __ldg(gg + k) * rsqrtf(v + EPSB);
            c = __ldg(bb + k) - m * a;
        } else if (k == 2 * DX) {
            c = __ldg(bb + k);
        }
        av[h] = a; cv[h] = c;
    }

    const float* xr0 = g_xT + (size_t)m0 * TT * DX;
    const float* xr8 = g_xT + (size_t)(m0 + 8) * TT * DX;
    float f[8];
#pragma unroll
    for (int h = 0; h < 4; h++) {
        int k = kb + (h >> 1) * 8 + (h & 1);
        float rv0 = 0.f, rv1 = 0.f;
        if (k < DX)          { rv0 = xr0[(size_t)it * DX + k];        rv1 = xr8[(size_t)it * DX + k]; }
        else if (k < 2 * DX) { rv0 = xr0[(size_t)i * DX + (k - DX)];  rv1 = xr8[(size_t)i * DX + (k - DX)]; }
        float v0 = fmaf(rv0, av[h], cv[h]);
        float v1 = fmaf(rv1, av[h], cv[h]);
        // f order: f0=(r,2q) f1=(r,2q+1) f2=(r+8,2q) f3=(r+8,2q+1) f4..f7 = +8k
        int base = (h >> 1) * 4 + (h & 1);
        f[base] = v0;
        f[base + 2] = v1;
    }
    float* t0 = g_bufB + (size_t)i * A_IN_STRIDE;
    float* dst = t0 + ((size_t)(mt * KT16_IN + kt) * 32 + lane) * 8;
    ((float4*)dst)[0] = make_float4(f[0], f[1], f[2], f[3]);
    ((float4*)dst)[1] = make_float4(f[4], f[5], f[6], f[7]);
}

// ---------------- 3xBF16 GEMM: 128x128 CTA (256 thr, 4m x 2n warps), 2 CTAs/SM ----------------
__global__ __launch_bounds__(256, 2)
void gemm_mma_kernel(const float* __restrict__ ApBase, int Kt, int chunks, size_t aStride,
                     const uint32_t* __restrict__ Bp,
                     const float* __restrict__ csPB, const float* __restrict__ cqPB,
                     const float* __restrict__ gg, const float* __restrict__ bb,
                     const float* __restrict__ bias,
                     float* __restrict__ outBase, size_t oStride, int ldo, int tile_out, int do_tanh,
                     float* __restrict__ csumB, float* __restrict__ csqB) {
    extern __shared__ float smf[];
    __shared__ float sa[DH], sc[DH];
    __shared__ float scol[128], ssq[128];
    const uint32_t sbase = smem_u32(smf);
    const int tid = threadIdx.x;
    const int step = blockIdx.z;
    const int mt0 = blockIdx.y * 8;      // 8 mtiles(16) = 128 rows per CTA
    const int nt0 = blockIdx.x * 16;     // 16 ntiles(8) = 128 cols per CTA
    const int w = tid >> 5, lane = tid & 31;
    const int wm = w & 3, wn2 = w >> 2;
    const bool fold = (csPB != nullptr);

    const float* Ap = ApBase + (size_t)step * aStride;
    float* out = outBase + (size_t)step * oStride;

    if (fold) {
        const float* csP = csPB + (size_t)step * DH;
        const float* cqP = cqPB + (size_t)step * DH;
        for (int k = tid; k < Kt * 16; k += 256) {
            float m = __ldg(csP + k) * (1.f / BATCH);
            float v = __ldg(cqP + k) * (1.f / BATCH) - m * m;
            if (v < 0.f) v = 0.f;
            float a = __ldg(gg + k) * rsqrtf(v + EPSB);
            sa[k] = a;
            sc[k] = __ldg(bb + k) - m * a;
        }
    } else {
        for (int k = tid; k < Kt * 16; k += 256) { sa[k] = 1.f; sc[k] = 0.f; }
    }
    __syncthreads();

    // stage: A [mt(8)][kt16(2)][lane][8f] = 16KB | B [nt(16)][kt16(2)][lane][4w] = 16KB
#define LOAD_A(kc_, st_)                                                         \
    {                                                                            \
        uint32_t base_ = sbase + (st_) * STAGE;                                  \
        _Pragma("unroll")                                                        \
        for (int i_ = 0; i_ < 4; i_++) {                                         \
            int idx_ = i_ * 256 + tid;                                           \
            int mt_ = idx_ >> 7, kt_ = (idx_ >> 6) & 1, ln_ = (idx_ >> 1) & 31, hf_ = idx_ & 1; \
            const float* src_ = Ap + (((size_t)(mt0 + mt_) * Kt + (kc_) * 2 + kt_) * 32 + ln_) * 8 + hf_ * 4; \
            cpasync16(base_ + (uint32_t)(((mt_ * 2 + kt_) * 32 + ln_) * 32 + hf_ * 16), src_); \
        }                                                                        \
    }
#define LOAD_B(kc_, st_)                                                         \
    {                                                                            \
        uint32_t bb_ = sbase + (st_) * STAGE + 16384;                            \
        _Pragma("unroll")                                                        \
        for (int i_ = 0; i_ < 4; i_++) {                                         \
            int idx_ = i_ * 256 + tid;                                           \
            int nt_ = idx_ >> 6, kt_ = (idx_ >> 5) & 1, ln_ = idx_ & 31;         \
            const uint32_t* src_ = Bp + ((size_t)(nt0 + nt_) * Kt + (kc_) * 2 + kt_) * 128 + ln_ * 4; \
            cpasync16(bb_ + (uint32_t)(((nt_ * 2 + kt_) * 32 + ln_) * 16), src_); \
        }                                                                        \
    }

    float acc[2][8][4];
#pragma unroll
    for (int mi = 0; mi < 2; mi++)
#pragma unroll
        for (int ni = 0; ni < 8; ni++)
#pragma unroll
            for (int r = 0; r < 4; r++) acc[mi][ni][r] = 0.f;

    LOAD_A(0, 0);
    LOAD_B(0, 0);
    CP_COMMIT();

    for (int kc = 0; kc < chunks; kc++) {
        const int st = kc & 1;
        if (kc + 1 < chunks) {
            LOAD_A(kc + 1, st ^ 1);
            LOAD_B(kc + 1, st ^ 1);
            CP_COMMIT();
            CP_WAIT1();
        } else {
            CP_WAIT0();
        }
        __syncthreads();

        const uint32_t abase = sbase + st * STAGE;
        const uint32_t bbase = abase + 16384;
#pragma unroll
        for (int kt = 0; kt < 2; kt++) {
            const int kg = (kc * 2 + kt) * 16 + 2 * (lane & 3);
            const float fa0 = sa[kg],     fc0 = sc[kg];
            const float fa1 = sa[kg + 1], fc1 = sc[kg + 1];
            const float fa8 = sa[kg + 8], fc8 = sc[kg + 8];
            const float fa9 = sa[kg + 9], fc9 = sc[kg + 9];

            uint32_t ah[2][4], al[2][4];
#pragma unroll
            for (int mi = 0; mi < 2; mi++) {
                int mt = wm * 2 + mi;
                float f[8];
                uint32_t ad = abase + (uint32_t)(((mt * 2 + kt) * 32 + lane) * 32);
                lds128f(f, ad);
                lds128f(f + 4, ad + 16);
                float g0 = fmaf(f[0], fa0, fc0);
                float g1 = fmaf(f[1], fa1, fc1);
                float g2 = fmaf(f[2], fa0, fc0);
                float g3 = fmaf(f[3], fa1, fc1);
                float g4 = fmaf(f[4], fa8, fc8);
                float g5 = fmaf(f[5], fa9, fc9);
                float g6 = fmaf(f[6], fa8, fc8);
                float g7 = fmaf(f[7], fa9, fc9);
                split_pair(g0, g1, ah[mi][0], al[mi][0]);   // a0: (r, 2q/2q+1)
                split_pair(g2, g3, ah[mi][1], al[mi][1]);   // a1: (r+8, ...)
                split_pair(g4, g5, ah[mi][2], al[mi][2]);   // a2: (r, +8)
                split_pair(g6, g7, ah[mi][3], al[mi][3]);   // a3: (r+8, +8)
            }
#pragma unroll
            for (int h = 0; h < 2; h++) {
                uint32_t bf[4][4];
#pragma unroll
                for (int ni = 0; ni < 4; ni++) {
                    int nt = wn2 * 8 + h * 4 + ni;
                    lds128(bf[ni], bbase + (uint32_t)(((nt * 2 + kt) * 32 + lane) * 16));
                }
#pragma unroll
                for (int ni = 0; ni < 4; ni++)
#pragma unroll
                    for (int mi = 0; mi < 2; mi++)
                        mma16(acc[mi][h * 4 + ni], ah[mi], bf[ni][0], bf[ni][1]);   // hi*hi
#pragma unroll
                for (int ni = 0; ni < 4; ni++)
#pragma unroll
                    for (int mi = 0; mi < 2; mi++)
                        mma16(acc[mi][h * 4 + ni], al[mi], bf[ni][0], bf[ni][1]);   // lo*hi
#pragma unroll
                for (int ni = 0; ni < 4; ni++)
#pragma unroll
                    for (int mi = 0; mi < 2; mi++)
                        mma16(acc[mi][h * 4 + ni], ah[mi], bf[ni][2], bf[ni][3]);   // hi*lo
            }
        }
        __syncthreads();
    }

    const int r = lane >> 2, q = lane & 3;
    float colacc[8][4];
#pragma unroll
    for (int ni = 0; ni < 8; ni++)
#pragma unroll
        for (int u = 0; u < 4; u++) colacc[ni][u] = 0.f;

#pragma unroll
    for (int mi = 0; mi < 2; mi++) {
        int m = blockIdx.y * 128 + wm * 32 + mi * 16 + r;
#pragma unroll
        for (int ni = 0; ni < 8; ni++) {
            int n = nt0 * 8 + wn2 * 64 + ni * 8 + 2 * q;
            float b0 = __ldg(bias + n), b1 = __ldg(bias + n + 1);
            float v0 = acc[mi][ni][0] + b0;
            float v1 = acc[mi][ni][1] + b1;
            float v2 = acc[mi][ni][2] + b0;
            float v3 = acc[mi][ni][3] + b1;
            if (do_tanh) {
                v0 = fast_tanh(v0); v1 = fast_tanh(v1);
                v2 = fast_tanh(v2); v3 = fast_tanh(v3);
            }
            colacc[ni][0] += v0 + v2;
            colacc[ni][1] += v1 + v3;
            colacc[ni][2] += v0 * v0 + v2 * v2;
            colacc[ni][3] += v1 * v1 + v3 * v3;
            if (tile_out) {
                // next-layer A layout: [mt16][kt16(KT16_H)][lane][8]
                int base = ((((m >> 4) * KT16_H + (n >> 4)) * 32
                           + ((m & 7) << 2) + ((n & 7) >> 1)) << 3)
                         + ((n >> 3) & 1) * 4;
                *(float2*)(out + base)     = make_float2(v0, v1);  // (m, n/n+1)
                *(float2*)(out + base + 2) = make_float2(v2, v3);  // (m+8, n/n+1)
            } else {
                *(float2*)(out + (size_t)m * ldo + n) = make_float2(v0, v1);
                *(float2*)(out + (size_t)(m + 8) * ldo + n) = make_float2(v2, v3);
            }
        }
    }

    if (csumB != nullptr) {
        float* csum = csumB + (size_t)step * DH;
        float* csq  = csqB + (size_t)step * DH;
        if (tid < 128) { scol[tid] = 0.f; ssq[tid] = 0.f; }
        __syncthreads();
#pragma unroll
        for (int ni = 0; ni < 8; ni++) {
            float a0 = colacc[ni][0], a1 = colacc[ni][1];
            float q0 = colacc[ni][2], q1 = colacc[ni][3];
#pragma unroll
            for (int off = 4; off < 32; off <<= 1) {
                a0 += __shfl_xor_sync(0xffffffffu, a0, off);
                a1 += __shfl_xor_sync(0xffffffffu, a1, off);
                q0 += __shfl_xor_sync(0xffffffffu, q0, off);
                q1 += __shfl_xor_sync(0xffffffffu, q1, off);
            }
            if (r == 0) {
                int cn = wn2 * 64 + ni * 8 + 2 * q;
                atomicAdd(&scol[cn], a0);
                atomicAdd(&scol[cn + 1], a1);
                atomicAdd(&ssq[cn], q0);
                atomicAdd(&ssq[cn + 1], q1);
            }
        }
        __syncthreads();
        if (tid < 128) {
            int col = blockIdx.x * 128 + tid;
            atomicAdd(csum + col, scol[tid]);
            atomicAdd(csq + col, ssq[tid]);
        }
    }
#undef LOAD_A
#undef LOAD_B
}

// ---------------- reductions / scatter / y recursion ----------------
__global__ void s_kernel() {
    int b = blockIdx.x, i = blockIdx.y, d = threadIdx.x;
    float zt = g_zt[((size_t)i * BATCH + b) * DD + d];
    float zd = (i > NDLY) ? g_zt[((size_t)(i - NDLY - 1) * BATCH + b) * DD + d] : 0.f;
    float dw = g_dWT[((size_t)b * NSTEP + i) * DD + d];
    float p1 = zt * zd;
    float p2 = zt * dw;
#pragma unroll
    for (int off = 16; off; off >>= 1) {
        p1 += __shfl_down_sync(0xffffffffu, p1, off);
        p2 += __shfl_down_sync(0xffffffffu, p2, off);
    }
    __shared__ float red[2][4];
    int w = d >> 5, lane = d & 31;
    if (lane == 0) { red[0][w] = p1; red[1][w] = p2; }
    __syncthreads();
    if (d == 0) {
        float s1 = red[0][0] + red[0][1] + red[0][2] + red[0][3];
        float s2 = red[1][0] + red[1][1] + red[1][2] + red[1][3];
        g_C1[i * BATCH + b] = s1 + 0.01f * g_xrow[b * TT + i + NDLY];
        g_S2[i * BATCH + b] = s2;
    }
}

__global__ void zscatter_kernel(float* __restrict__ z) {
    __shared__ float sm[NSTEP][DD + 1];
    int b = blockIdx.x;
    for (int q = threadIdx.x; q < NSTEP * DD; q += 256) {
        int i = q >> 7, d = q & 127;
        sm[i][d] = g_zt[((size_t)i * BATCH + b) * DD + d];
    }
    __syncthreads();
    for (int q = threadIdx.x; q < DD * TT; q += 256) {
        int d = q / TT, t = q - d * TT;
        float v = (t <= NDLY) ? 0.f : sm[t - NDLY - 1][d];
        z[(size_t)b * DD * TT + q] = v;
    }
}

__global__ void yrec_kernel(const float* __restrict__ y0, float* __restrict__ yt,
                            float* __restrict__ y) {
    int b = blockIdx.x * 256 + threadIdx.x;
    if (b >= BATCH) return;
    float y0v = __ldg(y0);
    float ycur = y0v;
    float yh[NSTEP];
    for (int t = 0; t <= NDLY; t++) y[b * TT + t] = y0v;
#pragma unroll 1
    for (int i = 0; i < NSTEP; i++) {
        float yd = (i <= NDLY) ? y0v : yh[i - NDLY - 1];
        float drv = -ycur + 0.1f * yd + g_C1[i * BATCH + b];
        ycur = ycur - drv * DTC + g_S2[i * BATCH + b];
        yh[i] = ycur;
        y[b * TT + NDLY + 1 + i] = ycur;
    }
    yt[b] = ycur;
}

// ---------------- host launch ----------------
static void* sym_addr_v(const void* sym) {
    void* p = nullptr;
    cudaGetSymbolAddress(&p, sym);
    return p;
}

extern "C" void kernel_launch(void* const* d_in, const int* in_sizes, int n_in,
                              void* d_out, int out_size) {
    const float* x        = (const float*)d_in[0];
    const float* dW       = (const float*)d_in[1];
    const float* y0       = (const float*)d_in[2];
    const float* bn_in_g  = (const float*)d_in[3];
    const float* bn_in_b  = (const float*)d_in[4];
    const float* W_in     = (const float*)d_in[5];
    const float* b_in     = (const float*)d_in[6];
    const float* Ws_h     = (const float*)d_in[7];
    const float* bs_h     = (const float*)d_in[8];
    const float* bns_g    = (const float*)d_in[9];
    const float* bns_b    = (const float*)d_in[10];
    const float* bn_out_g = (const float*)d_in[11];
    const float* bn_out_b = (const float*)d_in[12];
    const float* W_out    = (const float*)d_in[13];
    const float* b_out    = (const float*)d_in[14];

    float* yt = (float*)d_out;
    float* y  = yt + BATCH;
    float* z  = y + (size_t)BATCH * TT;

    float* bufA = (float*)sym_addr_v(g_bufA);
    float* bufB = (float*)sym_addr_v(g_bufB);
    uint32_t* Bsp = (uint32_t*)sym_addr_v(g_Bsp);
    float* zt  = (float*)sym_addr_v(g_zt);
    float* cs  = (float*)sym_addr_v(g_cs);
    float* cq  = (float*)sym_addr_v(g_cq);

    cudaFuncSetAttribute(gemm_mma_kernel, cudaFuncAttributeMaxDynamicSharedMemorySize, GEMM_SMEM);

    mega_setup_kernel<<<R0 + R1 + R2 + R3 + R4 + R5, 256>>>(x, dW, W_in, Ws_h, W_out);
    gather_all_kernel<<<dim3(576, NSTEP), 256>>>(bn_in_g, bn_in_b);

    dim3 gridH(8, 32, NSTEP);   // 128x128 tiles
    dim3 gridO(1, 32, NSTEP);

    // input layer (no fold): bufB -> bufA, stats cs[0]   (chunks = 18/2 = 9)
    gemm_mma_kernel<<<gridH, 256, GEMM_SMEM>>>(bufB, KT16_IN, KT16_IN / 2, A_IN_STRIDE,
                                               Bsp + BIN_OFF,
                                               nullptr, nullptr, nullptr, nullptr,
                                               b_in, bufA, A_H_STRIDE, 0, 1, 1,
                                               cs + 0 * NSTEP * DH, cq + 0 * NSTEP * DH);
    // hidden 1: bufA -> bufB   (chunks = 64/2 = 32)
    gemm_mma_kernel<<<gridH, 256, GEMM_SMEM>>>(bufA, KT16_H, KT16_H / 2, A_H_STRIDE,
                                               Bsp + BH_OFF,
                                               cs + 0 * NSTEP * DH, cq + 0 * NSTEP * DH,
                                               bns_g + 0 * DH, bns_b + 0 * DH,
                                               bs_h + 0 * DH, bufB, A_H_STRIDE, 0, 1, 1,
                                               cs + 1 * NSTEP * DH, cq + 1 * NSTEP * DH);
    // hidden 2: bufB -> bufA
    gemm_mma_kernel<<<gridH, 256, GEMM_SMEM>>>(bufB, KT16_H, KT16_H / 2, A_H_STRIDE,
                                               Bsp + BH_OFF + BH_SZ,
                                               cs + 1 * NSTEP * DH, cq + 1 * NSTEP * DH,
                                               bns_g + 1 * DH, bns_b + 1 * DH,
                                               bs_h + 1 * DH, bufA, A_H_STRIDE, 0, 1, 1,
                                               cs + 2 * NSTEP * DH, cq + 2 * NSTEP * DH);
    // hidden 3: bufA -> bufB
    gemm_mma_kernel<<<gridH, 256, GEMM_SMEM>>>(bufA, KT16_H, KT16_H / 2, A_H_STRIDE,
                                               Bsp + BH_OFF + 2 * BH_SZ,
                                               cs + 2 * NSTEP * DH, cq + 2 * NSTEP * DH,
                                               bns_g + 2 * DH, bns_b + 2 * DH,
                                               bs_h + 2 * DH, bufB, A_H_STRIDE, 0, 1, 1,
                                               cs + 3 * NSTEP * DH, cq + 3 * NSTEP * DH);
    // output layer: bufB -> zt (row-major, no tanh)
    gemm_mma_kernel<<<gridO, 256, GEMM_SMEM>>>(bufB, KT16_H, KT16_H / 2, A_H_STRIDE,
                                               Bsp + BOUT_OFF,
                                               cs + 3 * NSTEP * DH, cq + 3 * NSTEP * DH,
                                               bn_out_g, bn_out_b,
                                               b_out, zt, ZT_STRIDE, DD, 0, 0,
                                               nullptr, nullptr);

    s_kernel<<<dim3(BATCH, NSTEP), DD>>>();
    zscatter_kernel<<<BATCH, 256>>>(z);
    yrec_kernel<<<(BATCH + 255) / 256, 256>>>(y0, yt, y);
}